// round 14
// baseline (speedup 1.0000x reference)
#include <cuda_runtime.h>
#include <cuda_bf16.h>
#include <cstdint>

#define TOK 8192
#define SEQ 2048
#define DIM 512
#define NH  8
#define HDM 64
#define NL  4
#define FF  200
#define NB  4
#define FFP 256

// ---------------- device scratch (allocation-free) ----------------
__device__ float g_x[TOK*DIM];
__device__ float g_t[TOK*DIM];
__device__ float g_pe[SEQ*DIM];
__device__ __nv_bfloat16 g_xh[TOK*DIM];
__device__ __nv_bfloat16 g_xl[TOK*DIM];
__device__ __nv_bfloat16 g_qh[TOK*DIM];
__device__ __nv_bfloat16 g_ql[TOK*DIM];
__device__ __nv_bfloat16 g_kh[TOK*DIM];
__device__ __nv_bfloat16 g_kl[TOK*DIM];
__device__ __nv_bfloat16 g_vh[TOK*DIM];
__device__ __nv_bfloat16 g_vl[TOK*DIM];
__device__ __nv_bfloat16 g_yh[TOK*DIM];
__device__ __nv_bfloat16 g_yl[TOK*DIM];
__device__ __nv_bfloat16 g_hh[TOK*FFP];
__device__ __nv_bfloat16 g_hl[TOK*FFP];
#define LWSZ 1310720
__device__ __nv_bfloat16 g_wh[4*LWSZ];
__device__ __nv_bfloat16 g_wl[4*LWSZ];

// ---------------- helpers ----------------
__device__ __forceinline__ unsigned su32(const void* p) {
    return (unsigned)__cvta_generic_to_shared(p);
}
__device__ __forceinline__ void ldsm4(uint32_t* r, unsigned addr) {
    asm volatile("ldmatrix.sync.aligned.m8n8.x4.shared.b16 {%0,%1,%2,%3}, [%4];"
        : "=r"(r[0]), "=r"(r[1]), "=r"(r[2]), "=r"(r[3]) : "r"(addr));
}
__device__ __forceinline__ void ldsm4t(uint32_t* r, unsigned addr) {
    asm volatile("ldmatrix.sync.aligned.m8n8.x4.trans.shared.b16 {%0,%1,%2,%3}, [%4];"
        : "=r"(r[0]), "=r"(r[1]), "=r"(r[2]), "=r"(r[3]) : "r"(addr));
}
__device__ __forceinline__ void mma16816(float* c, const uint32_t* a, const uint32_t* b) {
    asm volatile("mma.sync.aligned.m16n8k16.row.col.f32.bf16.bf16.f32 "
        "{%0,%1,%2,%3}, {%4,%5,%6,%7}, {%8,%9}, {%0,%1,%2,%3};"
        : "+f"(c[0]), "+f"(c[1]), "+f"(c[2]), "+f"(c[3])
        : "r"(a[0]), "r"(a[1]), "r"(a[2]), "r"(a[3]), "r"(b[0]), "r"(b[1]));
}
__device__ __forceinline__ void bsplit(float v, __nv_bfloat16& h, __nv_bfloat16& l) {
    h = __float2bfloat16(v);
    l = __float2bfloat16(v - __bfloat162float(h));
}
__device__ __forceinline__ uint32_t bpack(__nv_bfloat16 a, __nv_bfloat16 b) {
    __nv_bfloat162 p = __nv_bfloat162(a, b);
    return *(uint32_t*)&p;
}
__device__ __forceinline__ void cpasync16(unsigned saddr, const void* gaddr) {
    asm volatile("cp.async.cg.shared.global [%0], [%1], 16;" :: "r"(saddr), "l"(gaddr));
}

// ---------------- fast exp2 on the FMA pipe (input <= 0) ----------------
__device__ __forceinline__ float exp2_fast(float t) {
    t = fmaxf(t, -126.0f);
    float z = t + 12582912.0f;
    int   ii = __float_as_int(z);
    float n  = z - 12582912.0f;
    float f  = t - n;
    float p  =            1.535336188319500e-4f;
    p = fmaf(p, f, 1.339887440266574e-3f);
    p = fmaf(p, f, 9.618437357674640e-3f);
    p = fmaf(p, f, 5.550332471162809e-2f);
    p = fmaf(p, f, 2.402264791363012e-1f);
    p = fmaf(p, f, 6.931472028550421e-1f);
    p = fmaf(p, f, 1.0f);
    return __int_as_float(__float_as_int(p) + (ii << 23));
}

// ---------------- positional encoding table + add ----------------
__global__ void pe_table_kernel(float* __restrict__ pe) {
    int idx = blockIdx.x * blockDim.x + threadIdx.x;
    if (idx >= SEQ*DIM) return;
    int d = idx & (DIM-1);
    int s = idx >> 9;
    int i2 = d & ~1;
    float div = expf((float)i2 * (-9.210340371976184f / (float)DIM));
    float ang = (float)s * div;
    pe[idx] = (d & 1) ? cosf(ang) : sinf(ang);
}
__global__ void posenc_kernel(const float* __restrict__ f, const float* __restrict__ pe,
                              float* __restrict__ x,
                              __nv_bfloat16* __restrict__ xh, __nv_bfloat16* __restrict__ xl) {
    int idx = blockIdx.x * blockDim.x + threadIdx.x;
    if (idx >= TOK*DIM) return;
    float v = f[idx] + pe[idx & (SEQ*DIM - 1)];
    x[idx] = v;
    __nv_bfloat16 h, l;
    bsplit(v, h, l);
    xh[idx] = h; xl[idx] = l;
}

// W [Kreal,Nreal] -> [Npad][Kpad] hi/lo, zero-padded; smem-tile transpose
__global__ void transpose_split_kernel(const float* __restrict__ W,
                                       int Kreal, int Nreal, int Kpad, int Npad,
                                       size_t wstride, size_t ostride,
                                       __nv_bfloat16* __restrict__ oh, __nv_bfloat16* __restrict__ ol) {
    __shared__ float tile[32][33];
    const float* Wl = W + (size_t)blockIdx.z * wstride;
    __nv_bfloat16* ohl = oh + (size_t)blockIdx.z * ostride;
    __nv_bfloat16* oll = ol + (size_t)blockIdx.z * ostride;
    int k0 = blockIdx.x * 32, n0 = blockIdx.y * 32;
    int tx = threadIdx.x & 31, ty = threadIdx.x >> 5;
    #pragma unroll
    for (int i = 0; i < 4; i++) {
        int k = k0 + ty + i*8;
        int n = n0 + tx;
        tile[ty + i*8][tx] = (k < Kreal && n < Nreal) ? Wl[(size_t)k * Nreal + n] : 0.f;
    }
    __syncthreads();
    #pragma unroll
    for (int i = 0; i < 4; i++) {
        int n = n0 + ty + i*8;
        int k = k0 + tx;
        float v = tile[tx][ty + i*8];
        __nv_bfloat16 h, l;
        bsplit(v, h, l);
        ohl[(size_t)n * Kpad + k] = h;
        oll[(size_t)n * Kpad + k] = l;
    }
}

// ---------------- GEMM core: 2-stage cp.async pipeline, 32-wide chunks -----
#define BST 80                   // smem row stride bytes (64B data + 16 pad)
#define STGB (128 * BST)         // 10240 per matrix
#define GSTG (4 * STGB)          // 40960 per stage
#define GEMM_SMEM (2 * GSTG)     // 81920 -> 2 CTAs/SM

template<int KTOT>
__device__ __forceinline__ void gemm_core(
    const __nv_bfloat16* Ah, const __nv_bfloat16* Al,
    const __nv_bfloat16* Bh, const __nv_bfloat16* Bl,
    int m0, int n0, char* smem, float acc[2][8][4]) {
    unsigned s0 = su32(smem);
    int tid = threadIdx.x;
    int wid = tid >> 5, lane = tid & 31;
    int warp_m = wid & 3, warp_n = wid >> 2;
    const int NC = KTOT / 32;

    int ld_r  = tid >> 2;                // 0..63 (x4 over 'it' -> 128 rows? no: slot = tid + it*256)
    // loader: 512 slots per matrix (128 rows x 4 x16B)
    #define GEMM_ISSUE(c, stg) do {                                                   \
        unsigned base = s0 + (unsigned)(stg) * GSTG;                                  \
        int k0b = (c) * 64;   /* bytes: 32 bf16 = 64B */                              \
        _Pragma("unroll")                                                             \
        for (int it = 0; it < 2; it++) {                                              \
            int slot = tid + it * 256;                                                \
            int r = slot >> 2;                                                        \
            int cb = (slot & 3) * 16;                                                 \
            size_t ga = (size_t)(m0 + r) * (KTOT*2) + k0b + cb;                       \
            size_t gb = (size_t)(n0 + r) * (KTOT*2) + k0b + cb;                       \
            unsigned so = base + (unsigned)(r * BST + cb);                            \
            cpasync16(so,            (const char*)Ah + ga);                           \
            cpasync16(so + STGB,     (const char*)Al + ga);                           \
            cpasync16(so + 2*STGB,   (const char*)Bh + gb);                           \
            cpasync16(so + 3*STGB,   (const char*)Bl + gb);                           \
        }                                                                             \
        asm volatile("cp.async.commit_group;" ::: "memory");                          \
    } while (0)

    GEMM_ISSUE(0, 0);
    for (int c = 0; c < NC; c++) {
        asm volatile("cp.async.wait_group 0;" ::: "memory");
        __syncthreads();
        if (c + 1 < NC) GEMM_ISSUE(c + 1, (c + 1) & 1);
        unsigned base = s0 + (unsigned)(c & 1) * GSTG;
        #pragma unroll
        for (int ks = 0; ks < 2; ks++) {
            int colb = ks * 32;
            uint32_t ah[2][4], al[2][4];
            #pragma unroll
            for (int mt = 0; mt < 2; mt++) {
                unsigned ra = base + (unsigned)((warp_m*32 + mt*16 + (lane & 15)) * BST
                                                 + colb + (lane >> 4) * 16);
                ldsm4(ah[mt], ra);
                ldsm4(al[mt], ra + STGB);
            }
            #pragma unroll
            for (int pr = 0; pr < 4; pr++) {
                unsigned rb = base + (unsigned)((warp_n*64 + pr*16 + (lane & 7) + ((lane >> 4) & 1) * 8) * BST
                                                 + colb + ((lane >> 3) & 1) * 16);
                uint32_t bh[4], bl[4];
                ldsm4(bh, rb + 2*STGB);
                ldsm4(bl, rb + 3*STGB);
                #pragma unroll
                for (int mt = 0; mt < 2; mt++) {
                    mma16816(acc[mt][2*pr],   ah[mt], bh);
                    mma16816(acc[mt][2*pr],   ah[mt], bl);
                    mma16816(acc[mt][2*pr],   al[mt], bh);
                    mma16816(acc[mt][2*pr+1], ah[mt], bh+2);
                    mma16816(acc[mt][2*pr+1], ah[mt], bl+2);
                    mma16816(acc[mt][2*pr+1], al[mt], bh+2);
                }
            }
        }
    }
    #undef GEMM_ISSUE
}

template<int OUTMODE>
__device__ __forceinline__ void gemm_epi(
    float acc[2][8][4], const float* bias, float* Cf,
    __nv_bfloat16* Ch, __nv_bfloat16* Cl, int m0, int n0, int Nn, int Nreal) {
    int tid = threadIdx.x;
    int wid = tid >> 5, lane = tid & 31;
    int warp_m = wid & 3, warp_n = wid >> 2;
    #pragma unroll
    for (int mt = 0; mt < 2; mt++) {
        int r0 = m0 + warp_m*32 + mt*16 + (lane >> 2);
        #pragma unroll
        for (int nt = 0; nt < 8; nt++) {
            int c0 = n0 + warp_n*64 + nt*8 + 2*(lane & 3);
            float b0 = (c0     < Nreal) ? bias[c0]     : 0.f;
            float b1 = (c0 + 1 < Nreal) ? bias[c0 + 1] : 0.f;
            float v0 = acc[mt][nt][0] + b0;
            float v1 = acc[mt][nt][1] + b1;
            float v2 = acc[mt][nt][2] + b0;
            float v3 = acc[mt][nt][3] + b1;
            if (OUTMODE == 0) {
                *(float2*)&Cf[(size_t)r0 * Nn + c0] = make_float2(v0, v1);
                *(float2*)&Cf[(size_t)(r0 + 8) * Nn + c0] = make_float2(v2, v3);
            } else {
                if (OUTMODE == 2) {
                    v0 = (c0     < Nreal) ? fmaxf(v0, 0.f) : 0.f;
                    v1 = (c0 + 1 < Nreal) ? fmaxf(v1, 0.f) : 0.f;
                    v2 = (c0     < Nreal) ? fmaxf(v2, 0.f) : 0.f;
                    v3 = (c0 + 1 < Nreal) ? fmaxf(v3, 0.f) : 0.f;
                }
                __nv_bfloat16 h0,l0,h1,l1,h2,l2,h3,l3;
                bsplit(v0,h0,l0); bsplit(v1,h1,l1); bsplit(v2,h2,l2); bsplit(v3,h3,l3);
                *(uint32_t*)&Ch[(size_t)r0 * Nn + c0] = bpack(h0,h1);
                *(uint32_t*)&Cl[(size_t)r0 * Nn + c0] = bpack(l0,l1);
                *(uint32_t*)&Ch[(size_t)(r0 + 8) * Nn + c0] = bpack(h2,h3);
                *(uint32_t*)&Cl[(size_t)(r0 + 8) * Nn + c0] = bpack(l2,l3);
            }
        }
    }
}

template<int KTOT, int OUTMODE>
__global__ __launch_bounds__(256, 2)
void mma_gemm(const __nv_bfloat16* __restrict__ Ah, const __nv_bfloat16* __restrict__ Al,
              const __nv_bfloat16* __restrict__ Bh, const __nv_bfloat16* __restrict__ Bl,
              const float* __restrict__ bias, float* __restrict__ Cf,
              __nv_bfloat16* __restrict__ Ch, __nv_bfloat16* __restrict__ Cl,
              int Nn, int Nreal) {
    extern __shared__ char smem[];
    int m0 = blockIdx.y * 128, n0 = blockIdx.x * 128;
    float acc[2][8][4] = {};
    gemm_core<KTOT>(Ah, Al, Bh, Bl, m0, n0, smem, acc);
    gemm_epi<OUTMODE>(acc, bias, Cf, Ch, Cl, m0, n0, Nn, Nreal);
}

// fused QKV: blockIdx.x = wsel*4 + ncol
__global__ __launch_bounds__(256, 2)
void qkv_gemm(const __nv_bfloat16* __restrict__ Ah, const __nv_bfloat16* __restrict__ Al,
              const __nv_bfloat16* __restrict__ Wqh, const __nv_bfloat16* __restrict__ Wql,
              const __nv_bfloat16* __restrict__ Wkh, const __nv_bfloat16* __restrict__ Wkl,
              const __nv_bfloat16* __restrict__ Wvh, const __nv_bfloat16* __restrict__ Wvl,
              const float* __restrict__ bq, const float* __restrict__ bk, const float* __restrict__ bv,
              __nv_bfloat16* __restrict__ qh, __nv_bfloat16* __restrict__ ql,
              __nv_bfloat16* __restrict__ kh, __nv_bfloat16* __restrict__ kl,
              __nv_bfloat16* __restrict__ vh, __nv_bfloat16* __restrict__ vl) {
    extern __shared__ char smem[];
    int wsel = blockIdx.x >> 2;
    int n0 = (blockIdx.x & 3) * 128;
    int m0 = blockIdx.y * 128;
    const __nv_bfloat16* Bh = (wsel == 0) ? Wqh : (wsel == 1) ? Wkh : Wvh;
    const __nv_bfloat16* Bl = (wsel == 0) ? Wql : (wsel == 1) ? Wkl : Wvl;
    const float* bias = (wsel == 0) ? bq : (wsel == 1) ? bk : bv;
    __nv_bfloat16* Ch = (wsel == 0) ? qh : (wsel == 1) ? kh : vh;
    __nv_bfloat16* Cl = (wsel == 0) ? ql : (wsel == 1) ? kl : vl;
    float acc[2][8][4] = {};
    gemm_core<512>(Ah, Al, Bh, Bl, m0, n0, smem, acc);
    gemm_epi<1>(acc, bias, nullptr, Ch, Cl, m0, n0, DIM, DIM);
}

// ---------------- HMMA flash attention: BQ=64, register-P, 2 CTAs/SM ------
#define ATS 72
#define SQH 0
#define SQL 4608
#define STG_BASE 9216
#define STG_SZ   18432
#define KOF 0
#define KLF 4608
#define VOF 9216
#define VLF 13824
#define ATTN_SMEM (46080 * 2)

__global__ __launch_bounds__(128, 2)
void attn_kernel(const __nv_bfloat16* __restrict__ qh, const __nv_bfloat16* __restrict__ ql,
                 const __nv_bfloat16* __restrict__ kh, const __nv_bfloat16* __restrict__ kl,
                 const __nv_bfloat16* __restrict__ vh, const __nv_bfloat16* __restrict__ vl,
                 __nv_bfloat16* __restrict__ yh, __nv_bfloat16* __restrict__ yl) {
    extern __shared__ __nv_bfloat16 smb[];
    unsigned sb = su32(smb);

    int tid = threadIdx.x;
    int wid = tid >> 5, lane = tid & 31;
    int qt_blk = blockIdx.x, h = blockIdx.y, n = blockIdx.z;
    const float SCALE_LOG2E = 0.125f * 1.4426950408889634f;

    int qbase = n * SEQ + qt_blk * 64;
    int hoff = h * HDM;

    #pragma unroll
    for (int it = 0; it < 4; it++) {
        int idx = tid + it * 128;
        int r = idx >> 3;
        int cb = (idx & 7) * 8;
        size_t ga = ((size_t)(qbase + r) * DIM + hoff + cb) * 2;
        *(uint4*)&smb[SQH + r * ATS + cb] = *(const uint4*)((const char*)qh + ga);
        *(uint4*)&smb[SQL + r * ATS + cb] = *(const uint4*)((const char*)ql + ga);
    }
    __syncthreads();

    uint32_t qfh[4][4], qfl[4][4];
    #pragma unroll
    for (int ks = 0; ks < 4; ks++) {
        unsigned ra = (unsigned)((wid*16 + (lane & 15)) * ATS
                                  + ks*16 + (lane >> 4) * 8) * 2u;
        ldsm4(qfh[ks], sb + SQH*2 + ra);
        ldsm4(qfl[ks], sb + SQL*2 + ra);
    }

    int ld_r  = tid >> 3;
    int ld_cb = (tid & 7) * 8;
    #define LOAD_KV_ASYNC(sidx, ktile) do {                                           \
        int sbase = STG_BASE + (sidx) * STG_SZ;                                       \
        int kb = n * SEQ + (ktile) * 64;                                              \
        _Pragma("unroll")                                                             \
        for (int it = 0; it < 4; it++) {                                              \
            int r = ld_r + it * 16;                                                   \
            size_t ga = ((size_t)(kb + r) * DIM + hoff + ld_cb) * 2;                  \
            unsigned so = sb + (unsigned)(sbase + r * ATS + ld_cb) * 2u;              \
            cpasync16(so + KOF*2, (const char*)kh + ga);                              \
            cpasync16(so + KLF*2, (const char*)kl + ga);                              \
            cpasync16(so + VOF*2, (const char*)vh + ga);                              \
            cpasync16(so + VLF*2, (const char*)vl + ga);                              \
        }                                                                             \
        asm volatile("cp.async.commit_group;" ::: "memory");                          \
    } while (0)

    float o[8][4] = {};
    float m0r = -1e30f, m1r = -1e30f, l0r = 0.f, l1r = 0.f;

    const int NT = SEQ / 64;
    LOAD_KV_ASYNC(0, 0);

    for (int kt = 0; kt < NT; kt++) {
        int cur = kt & 1;
        if (kt + 1 < NT) {
            LOAD_KV_ASYNC(cur ^ 1, kt + 1);
            asm volatile("cp.async.wait_group 1;" ::: "memory");
        } else {
            asm volatile("cp.async.wait_group 0;" ::: "memory");
        }
        __syncthreads();
        int sbase = STG_BASE + cur * STG_SZ;
        unsigned skh = sb + (unsigned)(sbase + KOF) * 2u;
        unsigned skl = sb + (unsigned)(sbase + KLF) * 2u;
        unsigned svh = sb + (unsigned)(sbase + VOF) * 2u;
        unsigned svl = sb + (unsigned)(sbase + VLF) * 2u;

        float s[8][4] = {};
        #pragma unroll
        for (int ks = 0; ks < 4; ks++) {
            #pragma unroll
            for (int pr = 0; pr < 4; pr++) {
                unsigned rb = (unsigned)((pr*16 + (lane & 7) + ((lane >> 4) & 1) * 8) * ATS
                                          + ks*16 + ((lane >> 3) & 1) * 8) * 2u;
                uint32_t bh[4], bl[4];
                ldsm4(bh, skh + rb);
                ldsm4(bl, skl + rb);
                mma16816(s[2*pr],   qfh[ks], bh);
                mma16816(s[2*pr],   qfh[ks], bl);
                mma16816(s[2*pr],   qfl[ks], bh);
                mma16816(s[2*pr+1], qfh[ks], bh+2);
                mma16816(s[2*pr+1], qfh[ks], bl+2);
                mma16816(s[2*pr+1], qfl[ks], bh+2);
            }
        }

        float mx0 = -1e30f, mx1 = -1e30f;
        #pragma unroll
        for (int nt = 0; nt < 8; nt++) {
            s[nt][0] *= SCALE_LOG2E; s[nt][1] *= SCALE_LOG2E;
            s[nt][2] *= SCALE_LOG2E; s[nt][3] *= SCALE_LOG2E;
            mx0 = fmaxf(mx0, fmaxf(s[nt][0], s[nt][1]));
            mx1 = fmaxf(mx1, fmaxf(s[nt][2], s[nt][3]));
        }
        mx0 = fmaxf(mx0, __shfl_xor_sync(0xffffffffu, mx0, 1));
        mx0 = fmaxf(mx0, __shfl_xor_sync(0xffffffffu, mx0, 2));
        mx1 = fmaxf(mx1, __shfl_xor_sync(0xffffffffu, mx1, 1));
        mx1 = fmaxf(mx1, __shfl_xor_sync(0xffffffffu, mx1, 2));
        float nm0 = fmaxf(m0r, mx0), nm1 = fmaxf(m1r, mx1);
        float corr0 = exp2_fast(m0r - nm0), corr1 = exp2_fast(m1r - nm1);
        m0r = nm0; m1r = nm1;
        float rs0 = 0.f, rs1 = 0.f;
        uint32_t pah[4][4], pal[4][4];
        #pragma unroll
        for (int nt = 0; nt < 8; nt++) {
            float p0 = exp2_fast(s[nt][0] - nm0);
            float p1 = exp2_fast(s[nt][1] - nm0);
            float p2 = exp2_fast(s[nt][2] - nm1);
            float p3 = exp2_fast(s[nt][3] - nm1);
            rs0 += p0 + p1; rs1 += p2 + p3;
            o[nt][0] *= corr0; o[nt][1] *= corr0;
            o[nt][2] *= corr1; o[nt][3] *= corr1;
            __nv_bfloat16 h0,l0,h1,l1,h2,l2,h3,l3;
            bsplit(p0,h0,l0); bsplit(p1,h1,l1); bsplit(p2,h2,l2); bsplit(p3,h3,l3);
            int ks = nt >> 1, half = (nt & 1) * 2;
            pah[ks][half + 0] = bpack(h0,h1);
            pah[ks][half + 1] = bpack(h2,h3);
            pal[ks][half + 0] = bpack(l0,l1);
            pal[ks][half + 1] = bpack(l2,l3);
        }
        rs0 += __shfl_xor_sync(0xffffffffu, rs0, 1);
        rs0 += __shfl_xor_sync(0xffffffffu, rs0, 2);
        rs1 += __shfl_xor_sync(0xffffffffu, rs1, 1);
        rs1 += __shfl_xor_sync(0xffffffffu, rs1, 2);
        l0r = l0r * corr0 + rs0;
        l1r = l1r * corr1 + rs1;

        #pragma unroll
        for (int ks = 0; ks < 4; ks++) {
            #pragma unroll
            for (int pr = 0; pr < 4; pr++) {
                unsigned rv = (unsigned)((ks*16 + (lane & 7) + ((lane >> 3) & 1) * 8) * ATS
                                          + pr*16 + ((lane >> 4) & 1) * 8) * 2u;
                uint32_t bh[4], bl[4];
                ldsm4t(bh, svh + rv);
                ldsm4t(bl, svl + rv);
                mma16816(o[2*pr],   pah[ks], bh);
                mma16816(o[2*pr],   pah[ks], bl);
                mma16816(o[2*pr],   pal[ks], bh);
                mma16816(o[2*pr+1], pah[ks], bh+2);
                mma16816(o[2*pr+1], pah[ks], bl+2);
                mma16816(o[2*pr+1], pal[ks], bh+2);
            }
        }
        __syncthreads();
    }

    float inv0 = 1.f / l0r, inv1 = 1.f / l1r;
    int r0 = wid*16 + (lane >> 2);
    int pc = 2 * (lane & 3);
    int rg = qbase + r0;
    int c0 = hoff + pc;
    #pragma unroll
    for (int nt = 0; nt < 8; nt++) {
        float v0 = o[nt][0] * inv0, v1 = o[nt][1] * inv0;
        float v2 = o[nt][2] * inv1, v3 = o[nt][3] * inv1;
        __nv_bfloat16 h0,l0,h1,l1,h2,l2,h3,l3;
        bsplit(v0,h0,l0); bsplit(v1,h1,l1); bsplit(v2,h2,l2); bsplit(v3,h3,l3);
        *(uint32_t*)&yh[(size_t)rg * DIM + c0 + nt*8] = bpack(h0,h1);
        *(uint32_t*)&yl[(size_t)rg * DIM + c0 + nt*8] = bpack(l0,l1);
        *(uint32_t*)&yh[(size_t)(rg+8) * DIM + c0 + nt*8] = bpack(h2,h3);
        *(uint32_t*)&yl[(size_t)(rg+8) * DIM + c0 + nt*8] = bpack(l2,l3);
    }
}

// ---------------- fused residual + LayerNorm (vectorized, +split out) ------
__global__ void ln_kernel(const float* __restrict__ x, const float* __restrict__ r,
                          const float* __restrict__ w, const float* __restrict__ b,
                          float* __restrict__ out,
                          __nv_bfloat16* __restrict__ oh, __nv_bfloat16* __restrict__ ol) {
    int row = blockIdx.x;
    int tid = threadIdx.x;
    const float4* x4 = (const float4*)(x + (size_t)row * DIM);
    const float4* r4 = (const float4*)(r + (size_t)row * DIM);
    float4 xv = x4[tid];
    float4 rv = r4[tid];
    float v0 = xv.x + rv.x, v1 = xv.y + rv.y, v2 = xv.z + rv.z, v3 = xv.w + rv.w;
    float sum = (v0 + v1) + (v2 + v3);
    __shared__ float red1[4], red2[4];
    #pragma unroll
    for (int off = 16; off; off >>= 1) sum += __shfl_xor_sync(0xffffffffu, sum, off);
    if ((tid & 31) == 0) red1[tid >> 5] = sum;
    __syncthreads();
    sum = red1[0] + red1[1] + red1[2] + red1[3];
    float mean = sum * (1.f / DIM);
    float d0 = v0 - mean, d1 = v1 - mean, d2 = v2 - mean, d3 = v3 - mean;
    float vs = (d0*d0 + d1*d1) + (d2*d2 + d3*d3);
    #pragma unroll
    for (int off = 16; off; off >>= 1) vs += __shfl_xor_sync(0xffffffffu, vs, off);
    if ((tid & 31) == 0) red2[tid >> 5] = vs;
    __syncthreads();
    vs = red2[0] + red2[1] + red2[2] + red2[3];
    float rstd = rsqrtf(vs * (1.f / DIM) + 1e-5f);
    float4 wv = ((const float4*)w)[tid];
    float4 bv = ((const float4*)b)[tid];
    float o0 = d0 * rstd * wv.x + bv.x;
    float o1 = d1 * rstd * wv.y + bv.y;
    float o2 = d2 * rstd * wv.z + bv.z;
    float o3 = d3 * rstd * wv.w + bv.w;
    ((float4*)(out + (size_t)row * DIM))[tid] = make_float4(o0, o1, o2, o3);
    __nv_bfloat16 h0,l0,h1,l1,h2,l2,h3,l3;
    bsplit(o0,h0,l0); bsplit(o1,h1,l1); bsplit(o2,h2,l2); bsplit(o3,h3,l3);
    uint2 hp = make_uint2(bpack(h0,h1), bpack(h2,h3));
    uint2 lp = make_uint2(bpack(l0,l1), bpack(l2,l3));
    ((uint2*)(oh + (size_t)row * DIM))[tid] = hp;
    ((uint2*)(ol + (size_t)row * DIM))[tid] = lp;
}

// ---------------- host ----------------
extern "C" void kernel_launch(void* const* d_in, const int* in_sizes, int n_in,
                              void* d_out, int out_size) {
    const float* features = (const float*)d_in[0];
    const float* Wq = (const float*)d_in[1];
    const float* bq = (const float*)d_in[2];
    const float* Wk = (const float*)d_in[3];
    const float* bk = (const float*)d_in[4];
    const float* Wv = (const float*)d_in[5];
    const float* bv = (const float*)d_in[6];
    const float* Wo = (const float*)d_in[7];
    const float* bo = (const float*)d_in[8];
    const float* W1 = (const float*)d_in[9];
    const float* b1 = (const float*)d_in[10];
    const float* W2 = (const float*)d_in[11];
    const float* b2 = (const float*)d_in[12];
    const float* ln1w = (const float*)d_in[13];
    const float* ln1b = (const float*)d_in[14];
    const float* ln2w = (const float*)d_in[15];
    const float* ln2b = (const float*)d_in[16];
    float* out = (float*)d_out;

    float *x, *t, *pe;
    __nv_bfloat16 *xh, *xl, *qh, *ql, *kh, *kl, *vh, *vl, *yh, *yl, *hh, *hl, *wh, *wl;
    cudaGetSymbolAddress((void**)&x, g_x);
    cudaGetSymbolAddress((void**)&t, g_t);
    cudaGetSymbolAddress((void**)&pe, g_pe);
    cudaGetSymbolAddress((void**)&xh, g_xh);
    cudaGetSymbolAddress((void**)&xl, g_xl);
    cudaGetSymbolAddress((void**)&qh, g_qh);
    cudaGetSymbolAddress((void**)&ql, g_ql);
    cudaGetSymbolAddress((void**)&kh, g_kh);
    cudaGetSymbolAddress((void**)&kl, g_kl);
    cudaGetSymbolAddress((void**)&vh, g_vh);
    cudaGetSymbolAddress((void**)&vl, g_vl);
    cudaGetSymbolAddress((void**)&yh, g_yh);
    cudaGetSymbolAddress((void**)&yl, g_yl);
    cudaGetSymbolAddress((void**)&hh, g_hh);
    cudaGetSymbolAddress((void**)&hl, g_hl);
    cudaGetSymbolAddress((void**)&wh, g_wh);
    cudaGetSymbolAddress((void**)&wl, g_wl);

    cudaFuncSetAttribute(attn_kernel, cudaFuncAttributeMaxDynamicSharedMemorySize, ATTN_SMEM);
    cudaFuncSetAttribute(qkv_gemm, cudaFuncAttributeMaxDynamicSharedMemorySize, GEMM_SMEM);
    cudaFuncSetAttribute(mma_gemm<512,0>, cudaFuncAttributeMaxDynamicSharedMemorySize, GEMM_SMEM);
    cudaFuncSetAttribute(mma_gemm<512,2>, cudaFuncAttributeMaxDynamicSharedMemorySize, GEMM_SMEM);
    cudaFuncSetAttribute(mma_gemm<256,0>, cudaFuncAttributeMaxDynamicSharedMemorySize, GEMM_SMEM);

    const size_t OQ = 0, OK = 262144, OV = 524288, OO = 786432, O1 = 1048576, O2 = 1179648;

    dim3 gW(16, 16, NL);
    dim3 gW1(16, 8, NL);
    dim3 gW2(8, 16, NL);
    transpose_split_kernel<<<gW, 256>>>(Wq, 512, 512, 512, 512, (size_t)DIM*DIM, LWSZ, wh + OQ, wl + OQ);
    transpose_split_kernel<<<gW, 256>>>(Wk, 512, 512, 512, 512, (size_t)DIM*DIM, LWSZ, wh + OK, wl + OK);
    transpose_split_kernel<<<gW, 256>>>(Wv, 512, 512, 512, 512, (size_t)DIM*DIM, LWSZ, wh + OV, wl + OV);
    transpose_split_kernel<<<gW, 256>>>(Wo, 512, 512, 512, 512, (size_t)DIM*DIM, LWSZ, wh + OO, wl + OO);
    transpose_split_kernel<<<gW1, 256>>>(W1, 512, FF, 512, FFP, (size_t)DIM*FF, LWSZ, wh + O1, wl + O1);
    transpose_split_kernel<<<gW2, 256>>>(W2, FF, 512, FFP, 512, (size_t)FF*DIM, LWSZ, wh + O2, wl + O2);

    pe_table_kernel<<<(SEQ*DIM + 255) / 256, 256>>>(pe);
    posenc_kernel<<<(TOK*DIM + 255) / 256, 256>>>(features, pe, x, xh, xl);

    dim3 gQKV(12, TOK/128);
    dim3 gD(4, TOK/128);
    dim3 gF1(2, TOK/128);
    dim3 gA(SEQ/64, NH, NB);

    for (int l = 0; l < NL; l++) {
        size_t base = (size_t)l * LWSZ;
        qkv_gemm<<<gQKV, 256, GEMM_SMEM>>>(xh, xl,
            wh+base+OQ, wl+base+OQ, wh+base+OK, wl+base+OK, wh+base+OV, wl+base+OV,
            bq + l*DIM, bk + l*DIM, bv + l*DIM,
            qh, ql, kh, kl, vh, vl);
        attn_kernel<<<gA, 128, ATTN_SMEM>>>(qh, ql, kh, kl, vh, vl, yh, yl);
        mma_gemm<512,0><<<gD, 256, GEMM_SMEM>>>(yh, yl, wh+base+OO, wl+base+OO, bo + l*DIM, t, nullptr, nullptr, DIM, DIM);
        ln_kernel<<<TOK, 128>>>(x, t, ln1w + l*DIM, ln1b + l*DIM, x, xh, xl);
        mma_gemm<512,2><<<gF1, 256, GEMM_SMEM>>>(xh, xl, wh+base+O1, wl+base+O1, b1 + l*FF, nullptr, hh, hl, FFP, FF);
        mma_gemm<256,0><<<gD, 256, GEMM_SMEM>>>(hh, hl, wh+base+O2, wl+base+O2, b2 + l*DIM, t, nullptr, nullptr, DIM, DIM);
        float* lnout = (l == NL-1) ? out : x;
        ln_kernel<<<TOK, 128>>>(x, t, ln2w + l*DIM, ln2b + l*DIM, lnout, xh, xl);
    }
}

// round 15
// speedup vs baseline: 1.0796x; 1.0796x over previous
#include <cuda_runtime.h>
#include <cuda_bf16.h>
#include <cstdint>

#define TOK 8192
#define SEQ 2048
#define DIM 512
#define NH  8
#define HDM 64
#define NL  4
#define FF  200
#define NB  4
#define FFP 256

// ---------------- device scratch (allocation-free) ----------------
__device__ float g_x[TOK*DIM];
__device__ float g_t[TOK*DIM];
__device__ float g_pe[SEQ*DIM];
__device__ __nv_bfloat16 g_xh[TOK*DIM];
__device__ __nv_bfloat16 g_xl[TOK*DIM];
__device__ __nv_bfloat16 g_qh[TOK*DIM];
__device__ __nv_bfloat16 g_ql[TOK*DIM];
__device__ __nv_bfloat16 g_kh[TOK*DIM];
__device__ __nv_bfloat16 g_kl[TOK*DIM];
__device__ __nv_bfloat16 g_vh[TOK*DIM];
__device__ __nv_bfloat16 g_vl[TOK*DIM];
__device__ __nv_bfloat16 g_yh[TOK*DIM];
__device__ __nv_bfloat16 g_yl[TOK*DIM];
__device__ __nv_bfloat16 g_hh[TOK*FFP];
__device__ __nv_bfloat16 g_hl[TOK*FFP];
#define LWSZ 1310720
__device__ __nv_bfloat16 g_wh[4*LWSZ];
__device__ __nv_bfloat16 g_wl[4*LWSZ];

// ---------------- helpers ----------------
__device__ __forceinline__ unsigned su32(const void* p) {
    return (unsigned)__cvta_generic_to_shared(p);
}
__device__ __forceinline__ void ldsm4(uint32_t* r, unsigned addr) {
    asm volatile("ldmatrix.sync.aligned.m8n8.x4.shared.b16 {%0,%1,%2,%3}, [%4];"
        : "=r"(r[0]), "=r"(r[1]), "=r"(r[2]), "=r"(r[3]) : "r"(addr));
}
__device__ __forceinline__ void ldsm4t(uint32_t* r, unsigned addr) {
    asm volatile("ldmatrix.sync.aligned.m8n8.x4.trans.shared.b16 {%0,%1,%2,%3}, [%4];"
        : "=r"(r[0]), "=r"(r[1]), "=r"(r[2]), "=r"(r[3]) : "r"(addr));
}
__device__ __forceinline__ void mma16816(float* c, const uint32_t* a, const uint32_t* b) {
    asm volatile("mma.sync.aligned.m16n8k16.row.col.f32.bf16.bf16.f32 "
        "{%0,%1,%2,%3}, {%4,%5,%6,%7}, {%8,%9}, {%0,%1,%2,%3};"
        : "+f"(c[0]), "+f"(c[1]), "+f"(c[2]), "+f"(c[3])
        : "r"(a[0]), "r"(a[1]), "r"(a[2]), "r"(a[3]), "r"(b[0]), "r"(b[1]));
}
__device__ __forceinline__ void bsplit(float v, __nv_bfloat16& h, __nv_bfloat16& l) {
    h = __float2bfloat16(v);
    l = __float2bfloat16(v - __bfloat162float(h));
}
__device__ __forceinline__ uint32_t bpack(__nv_bfloat16 a, __nv_bfloat16 b) {
    __nv_bfloat162 p = __nv_bfloat162(a, b);
    return *(uint32_t*)&p;
}
__device__ __forceinline__ void cpasync16(unsigned saddr, const void* gaddr) {
    asm volatile("cp.async.cg.shared.global [%0], [%1], 16;" :: "r"(saddr), "l"(gaddr));
}

// ---------------- fast exp2 on the FMA pipe (input <= 0) ----------------
__device__ __forceinline__ float exp2_fast(float t) {
    t = fmaxf(t, -126.0f);
    float z = t + 12582912.0f;
    int   ii = __float_as_int(z);
    float n  = z - 12582912.0f;
    float f  = t - n;
    float p  =            1.535336188319500e-4f;
    p = fmaf(p, f, 1.339887440266574e-3f);
    p = fmaf(p, f, 9.618437357674640e-3f);
    p = fmaf(p, f, 5.550332471162809e-2f);
    p = fmaf(p, f, 2.402264791363012e-1f);
    p = fmaf(p, f, 6.931472028550421e-1f);
    p = fmaf(p, f, 1.0f);
    return __int_as_float(__float_as_int(p) + (ii << 23));
}

// ---------------- positional encoding table + add ----------------
__global__ void pe_table_kernel(float* __restrict__ pe) {
    int idx = blockIdx.x * blockDim.x + threadIdx.x;
    if (idx >= SEQ*DIM) return;
    int d = idx & (DIM-1);
    int s = idx >> 9;
    int i2 = d & ~1;
    float div = expf((float)i2 * (-9.210340371976184f / (float)DIM));
    float ang = (float)s * div;
    pe[idx] = (d & 1) ? cosf(ang) : sinf(ang);
}
__global__ void posenc_kernel(const float* __restrict__ f, const float* __restrict__ pe,
                              float* __restrict__ x,
                              __nv_bfloat16* __restrict__ xh, __nv_bfloat16* __restrict__ xl) {
    int idx = blockIdx.x * blockDim.x + threadIdx.x;
    if (idx >= TOK*DIM) return;
    float v = f[idx] + pe[idx & (SEQ*DIM - 1)];
    x[idx] = v;
    __nv_bfloat16 h, l;
    bsplit(v, h, l);
    xh[idx] = h; xl[idx] = l;
}

// W [Kreal,Nreal] -> [Npad][Kpad] hi/lo, zero-padded; smem-tile transpose
__global__ void transpose_split_kernel(const float* __restrict__ W,
                                       int Kreal, int Nreal, int Kpad, int Npad,
                                       size_t wstride, size_t ostride,
                                       __nv_bfloat16* __restrict__ oh, __nv_bfloat16* __restrict__ ol) {
    __shared__ float tile[32][33];
    const float* Wl = W + (size_t)blockIdx.z * wstride;
    __nv_bfloat16* ohl = oh + (size_t)blockIdx.z * ostride;
    __nv_bfloat16* oll = ol + (size_t)blockIdx.z * ostride;
    int k0 = blockIdx.x * 32, n0 = blockIdx.y * 32;
    int tx = threadIdx.x & 31, ty = threadIdx.x >> 5;
    #pragma unroll
    for (int i = 0; i < 4; i++) {
        int k = k0 + ty + i*8;
        int n = n0 + tx;
        tile[ty + i*8][tx] = (k < Kreal && n < Nreal) ? Wl[(size_t)k * Nreal + n] : 0.f;
    }
    __syncthreads();
    #pragma unroll
    for (int i = 0; i < 4; i++) {
        int n = n0 + ty + i*8;
        int k = k0 + tx;
        float v = tile[tx][ty + i*8];
        __nv_bfloat16 h, l;
        bsplit(v, h, l);
        ohl[(size_t)n * Kpad + k] = h;
        oll[(size_t)n * Kpad + k] = l;
    }
}

// ---------------- GEMM core (round-13 shape: 64-wide chunks) --------------
#define AST_B 144
#define TILE_B (128 * AST_B)
#define GEMM_SMEM (4 * TILE_B)

template<int KTOT>
__device__ __forceinline__ void gemm_core(
    const __nv_bfloat16* Ah, const __nv_bfloat16* Al,
    const __nv_bfloat16* Bh, const __nv_bfloat16* Bl,
    int m0, int n0, char* smem, float acc[2][8][4]) {
    char* pAh = smem;
    char* pAl = smem + TILE_B;
    char* pBh = smem + 2*TILE_B;
    char* pBl = smem + 3*TILE_B;
    unsigned sAh = su32(pAh), sAl = su32(pAl), sBh = su32(pBh), sBl = su32(pBl);
    int tid = threadIdx.x;
    int wid = tid >> 5, lane = tid & 31;
    int warp_m = wid & 3, warp_n = wid >> 2;

    for (int k0 = 0; k0 < KTOT; k0 += 64) {
        #pragma unroll
        for (int it = 0; it < 4; it++) {
            int chunk = tid + it * 256;
            int r = chunk >> 3;
            int cb = (chunk & 7) * 16;
            size_t ga = ((size_t)(m0 + r) * KTOT + k0) * 2 + cb;
            size_t gb = ((size_t)(n0 + r) * KTOT + k0) * 2 + cb;
            unsigned so = (unsigned)(r * AST_B + cb);
            cpasync16(sAh + so, (const char*)Ah + ga);
            cpasync16(sAl + so, (const char*)Al + ga);
            cpasync16(sBh + so, (const char*)Bh + gb);
            cpasync16(sBl + so, (const char*)Bl + gb);
        }
        asm volatile("cp.async.commit_group;" ::: "memory");
        asm volatile("cp.async.wait_group 0;" ::: "memory");
        __syncthreads();

        #pragma unroll
        for (int ks = 0; ks < 4; ks++) {
            int colb = ks * 32;
            uint32_t ah[2][4], al[2][4];
            #pragma unroll
            for (int mt = 0; mt < 2; mt++) {
                unsigned ra = (unsigned)((warp_m*32 + mt*16 + (lane & 15)) * AST_B
                                          + colb + (lane >> 4) * 16);
                ldsm4(ah[mt], sAh + ra);
                ldsm4(al[mt], sAl + ra);
            }
            #pragma unroll
            for (int pr = 0; pr < 4; pr++) {
                unsigned rb = (unsigned)((warp_n*64 + pr*16 + (lane & 7) + ((lane >> 4) & 1) * 8) * AST_B
                                          + colb + ((lane >> 3) & 1) * 16);
                uint32_t bh[4], bl[4];
                ldsm4(bh, sBh + rb);
                ldsm4(bl, sBl + rb);
                #pragma unroll
                for (int mt = 0; mt < 2; mt++) {
                    mma16816(acc[mt][2*pr],   ah[mt], bh);
                    mma16816(acc[mt][2*pr],   ah[mt], bl);
                    mma16816(acc[mt][2*pr],   al[mt], bh);
                    mma16816(acc[mt][2*pr+1], ah[mt], bh+2);
                    mma16816(acc[mt][2*pr+1], ah[mt], bl+2);
                    mma16816(acc[mt][2*pr+1], al[mt], bh+2);
                }
            }
        }
        __syncthreads();
    }
}

template<int OUTMODE>
__device__ __forceinline__ void gemm_epi(
    float acc[2][8][4], const float* bias, float* Cf,
    __nv_bfloat16* Ch, __nv_bfloat16* Cl, int m0, int n0, int Nn, int Nreal) {
    int tid = threadIdx.x;
    int wid = tid >> 5, lane = tid & 31;
    int warp_m = wid & 3, warp_n = wid >> 2;
    #pragma unroll
    for (int mt = 0; mt < 2; mt++) {
        int r0 = m0 + warp_m*32 + mt*16 + (lane >> 2);
        #pragma unroll
        for (int nt = 0; nt < 8; nt++) {
            int c0 = n0 + warp_n*64 + nt*8 + 2*(lane & 3);
            float b0 = (c0     < Nreal) ? bias[c0]     : 0.f;
            float b1 = (c0 + 1 < Nreal) ? bias[c0 + 1] : 0.f;
            float v0 = acc[mt][nt][0] + b0;
            float v1 = acc[mt][nt][1] + b1;
            float v2 = acc[mt][nt][2] + b0;
            float v3 = acc[mt][nt][3] + b1;
            if (OUTMODE == 0) {
                *(float2*)&Cf[(size_t)r0 * Nn + c0] = make_float2(v0, v1);
                *(float2*)&Cf[(size_t)(r0 + 8) * Nn + c0] = make_float2(v2, v3);
            } else {
                if (OUTMODE == 2) {
                    v0 = (c0     < Nreal) ? fmaxf(v0, 0.f) : 0.f;
                    v1 = (c0 + 1 < Nreal) ? fmaxf(v1, 0.f) : 0.f;
                    v2 = (c0     < Nreal) ? fmaxf(v2, 0.f) : 0.f;
                    v3 = (c0 + 1 < Nreal) ? fmaxf(v3, 0.f) : 0.f;
                }
                __nv_bfloat16 h0,l0,h1,l1,h2,l2,h3,l3;
                bsplit(v0,h0,l0); bsplit(v1,h1,l1); bsplit(v2,h2,l2); bsplit(v3,h3,l3);
                *(uint32_t*)&Ch[(size_t)r0 * Nn + c0] = bpack(h0,h1);
                *(uint32_t*)&Cl[(size_t)r0 * Nn + c0] = bpack(l0,l1);
                *(uint32_t*)&Ch[(size_t)(r0 + 8) * Nn + c0] = bpack(h2,h3);
                *(uint32_t*)&Cl[(size_t)(r0 + 8) * Nn + c0] = bpack(l2,l3);
            }
        }
    }
}

template<int KTOT, int OUTMODE>
__global__ __launch_bounds__(256, 2)
void mma_gemm(const __nv_bfloat16* __restrict__ Ah, const __nv_bfloat16* __restrict__ Al,
              const __nv_bfloat16* __restrict__ Bh, const __nv_bfloat16* __restrict__ Bl,
              const float* __restrict__ bias, float* __restrict__ Cf,
              __nv_bfloat16* __restrict__ Ch, __nv_bfloat16* __restrict__ Cl,
              int Nn, int Nreal) {
    extern __shared__ char smem[];
    int m0 = blockIdx.y * 128, n0 = blockIdx.x * 128;
    float acc[2][8][4] = {};
    gemm_core<KTOT>(Ah, Al, Bh, Bl, m0, n0, smem, acc);
    gemm_epi<OUTMODE>(acc, bias, Cf, Ch, Cl, m0, n0, Nn, Nreal);
}

// fused QKV: blockIdx.x = wsel*4 + ncol
__global__ __launch_bounds__(256, 2)
void qkv_gemm(const __nv_bfloat16* __restrict__ Ah, const __nv_bfloat16* __restrict__ Al,
              const __nv_bfloat16* __restrict__ Wqh, const __nv_bfloat16* __restrict__ Wql,
              const __nv_bfloat16* __restrict__ Wkh, const __nv_bfloat16* __restrict__ Wkl,
              const __nv_bfloat16* __restrict__ Wvh, const __nv_bfloat16* __restrict__ Wvl,
              const float* __restrict__ bq, const float* __restrict__ bk, const float* __restrict__ bv,
              __nv_bfloat16* __restrict__ qh, __nv_bfloat16* __restrict__ ql,
              __nv_bfloat16* __restrict__ kh, __nv_bfloat16* __restrict__ kl,
              __nv_bfloat16* __restrict__ vh, __nv_bfloat16* __restrict__ vl) {
    extern __shared__ char smem[];
    int wsel = blockIdx.x >> 2;
    int n0 = (blockIdx.x & 3) * 128;
    int m0 = blockIdx.y * 128;
    const __nv_bfloat16* Bh = (wsel == 0) ? Wqh : (wsel == 1) ? Wkh : Wvh;
    const __nv_bfloat16* Bl = (wsel == 0) ? Wql : (wsel == 1) ? Wkl : Wvl;
    const float* bias = (wsel == 0) ? bq : (wsel == 1) ? bk : bv;
    __nv_bfloat16* Ch = (wsel == 0) ? qh : (wsel == 1) ? kh : vh;
    __nv_bfloat16* Cl = (wsel == 0) ? ql : (wsel == 1) ? kl : vl;
    float acc[2][8][4] = {};
    gemm_core<512>(Ah, Al, Bh, Bl, m0, n0, smem, acc);
    gemm_epi<1>(acc, bias, nullptr, Ch, Cl, m0, n0, DIM, DIM);
}

// ---------------- HMMA flash attention: BQ=64, register-P (Ph only) -------
#define ATS 72
#define SQH 0
#define SQL 4608
#define STG_BASE 9216
#define STG_SZ   18432
#define KOF 0
#define KLF 4608
#define VOF 9216
#define VLF 13824
#define ATTN_SMEM (46080 * 2)

__global__ __launch_bounds__(128, 2)
void attn_kernel(const __nv_bfloat16* __restrict__ qh, const __nv_bfloat16* __restrict__ ql,
                 const __nv_bfloat16* __restrict__ kh, const __nv_bfloat16* __restrict__ kl,
                 const __nv_bfloat16* __restrict__ vh, const __nv_bfloat16* __restrict__ vl,
                 __nv_bfloat16* __restrict__ yh, __nv_bfloat16* __restrict__ yl) {
    extern __shared__ __nv_bfloat16 smb[];
    unsigned sb = su32(smb);

    int tid = threadIdx.x;
    int wid = tid >> 5, lane = tid & 31;
    int qt_blk = blockIdx.x, h = blockIdx.y, n = blockIdx.z;
    const float SCALE_LOG2E = 0.125f * 1.4426950408889634f;

    int qbase = n * SEQ + qt_blk * 64;
    int hoff = h * HDM;

    #pragma unroll
    for (int it = 0; it < 4; it++) {
        int idx = tid + it * 128;
        int r = idx >> 3;
        int cb = (idx & 7) * 8;
        size_t ga = ((size_t)(qbase + r) * DIM + hoff + cb) * 2;
        *(uint4*)&smb[SQH + r * ATS + cb] = *(const uint4*)((const char*)qh + ga);
        *(uint4*)&smb[SQL + r * ATS + cb] = *(const uint4*)((const char*)ql + ga);
    }
    __syncthreads();

    uint32_t qfh[4][4], qfl[4][4];
    #pragma unroll
    for (int ks = 0; ks < 4; ks++) {
        unsigned ra = (unsigned)((wid*16 + (lane & 15)) * ATS
                                  + ks*16 + (lane >> 4) * 8) * 2u;
        ldsm4(qfh[ks], sb + SQH*2 + ra);
        ldsm4(qfl[ks], sb + SQL*2 + ra);
    }

    int ld_r  = tid >> 3;
    int ld_cb = (tid & 7) * 8;
    #define LOAD_KV_ASYNC(sidx, ktile) do {                                           \
        int sbase = STG_BASE + (sidx) * STG_SZ;                                       \
        int kb = n * SEQ + (ktile) * 64;                                              \
        _Pragma("unroll")                                                             \
        for (int it = 0; it < 4; it++) {                                              \
            int r = ld_r + it * 16;                                                   \
            size_t ga = ((size_t)(kb + r) * DIM + hoff + ld_cb) * 2;                  \
            unsigned so = sb + (unsigned)(sbase + r * ATS + ld_cb) * 2u;              \
            cpasync16(so + KOF*2, (const char*)kh + ga);                              \
            cpasync16(so + KLF*2, (const char*)kl + ga);                              \
            cpasync16(so + VOF*2, (const char*)vh + ga);                              \
            cpasync16(so + VLF*2, (const char*)vl + ga);                              \
        }                                                                             \
        asm volatile("cp.async.commit_group;" ::: "memory");                          \
    } while (0)

    float o[8][4] = {};
    float m0r = -1e30f, m1r = -1e30f, l0r = 0.f, l1r = 0.f;

    const int NT = SEQ / 64;
    LOAD_KV_ASYNC(0, 0);

    for (int kt = 0; kt < NT; kt++) {
        int cur = kt & 1;
        if (kt + 1 < NT) {
            LOAD_KV_ASYNC(cur ^ 1, kt + 1);
            asm volatile("cp.async.wait_group 1;" ::: "memory");
        } else {
            asm volatile("cp.async.wait_group 0;" ::: "memory");
        }
        __syncthreads();
        int sbase = STG_BASE + cur * STG_SZ;
        unsigned skh = sb + (unsigned)(sbase + KOF) * 2u;
        unsigned skl = sb + (unsigned)(sbase + KLF) * 2u;
        unsigned svh = sb + (unsigned)(sbase + VOF) * 2u;
        unsigned svl = sb + (unsigned)(sbase + VLF) * 2u;

        // S = Q K^T (3-term split: full precision on logits)
        float s[8][4] = {};
        #pragma unroll
        for (int ks = 0; ks < 4; ks++) {
            #pragma unroll
            for (int pr = 0; pr < 4; pr++) {
                unsigned rb = (unsigned)((pr*16 + (lane & 7) + ((lane >> 4) & 1) * 8) * ATS
                                          + ks*16 + ((lane >> 3) & 1) * 8) * 2u;
                uint32_t bh[4], bl[4];
                ldsm4(bh, skh + rb);
                ldsm4(bl, skl + rb);
                mma16816(s[2*pr],   qfh[ks], bh);
                mma16816(s[2*pr],   qfh[ks], bl);
                mma16816(s[2*pr],   qfl[ks], bh);
                mma16816(s[2*pr+1], qfh[ks], bh+2);
                mma16816(s[2*pr+1], qfh[ks], bl+2);
                mma16816(s[2*pr+1], qfl[ks], bh+2);
            }
        }

        // online softmax -> pack Ph into A fragments (Pl dropped: weights
        // carry +-2^-10 zero-mean rounding; output error ~1e-5..1e-4)
        float mx0 = -1e30f, mx1 = -1e30f;
        #pragma unroll
        for (int nt = 0; nt < 8; nt++) {
            s[nt][0] *= SCALE_LOG2E; s[nt][1] *= SCALE_LOG2E;
            s[nt][2] *= SCALE_LOG2E; s[nt][3] *= SCALE_LOG2E;
            mx0 = fmaxf(mx0, fmaxf(s[nt][0], s[nt][1]));
            mx1 = fmaxf(mx1, fmaxf(s[nt][2], s[nt][3]));
        }
        mx0 = fmaxf(mx0, __shfl_xor_sync(0xffffffffu, mx0, 1));
        mx0 = fmaxf(mx0, __shfl_xor_sync(0xffffffffu, mx0, 2));
        mx1 = fmaxf(mx1, __shfl_xor_sync(0xffffffffu, mx1, 1));
        mx1 = fmaxf(mx1, __shfl_xor_sync(0xffffffffu, mx1, 2));
        float nm0 = fmaxf(m0r, mx0), nm1 = fmaxf(m1r, mx1);
        float corr0 = exp2_fast(m0r - nm0), corr1 = exp2_fast(m1r - nm1);
        m0r = nm0; m1r = nm1;
        float rs0 = 0.f, rs1 = 0.f;
        uint32_t pah[4][4];
        #pragma unroll
        for (int nt = 0; nt < 8; nt++) {
            float p0 = exp2_fast(s[nt][0] - nm0);
            float p1 = exp2_fast(s[nt][1] - nm0);
            float p2 = exp2_fast(s[nt][2] - nm1);
            float p3 = exp2_fast(s[nt][3] - nm1);
            rs0 += p0 + p1; rs1 += p2 + p3;
            o[nt][0] *= corr0; o[nt][1] *= corr0;
            o[nt][2] *= corr1; o[nt][3] *= corr1;
            __nv_bfloat16 h0 = __float2bfloat16(p0);
            __nv_bfloat16 h1 = __float2bfloat16(p1);
            __nv_bfloat16 h2 = __float2bfloat16(p2);
            __nv_bfloat16 h3 = __float2bfloat16(p3);
            int ks = nt >> 1, half = (nt & 1) * 2;
            pah[ks][half + 0] = bpack(h0,h1);
            pah[ks][half + 1] = bpack(h2,h3);
        }
        rs0 += __shfl_xor_sync(0xffffffffu, rs0, 1);
        rs0 += __shfl_xor_sync(0xffffffffu, rs0, 2);
        rs1 += __shfl_xor_sync(0xffffffffu, rs1, 1);
        rs1 += __shfl_xor_sync(0xffffffffu, rs1, 2);
        l0r = l0r * corr0 + rs0;
        l1r = l1r * corr1 + rs1;

        // O += Ph @ (Vh + Vl)
        #pragma unroll
        for (int ks = 0; ks < 4; ks++) {
            #pragma unroll
            for (int pr = 0; pr < 4; pr++) {
                unsigned rv = (unsigned)((ks*16 + (lane & 7) + ((lane >> 3) & 1) * 8) * ATS
                                          + pr*16 + ((lane >> 4) & 1) * 8) * 2u;
                uint32_t bh[4], bl[4];
                ldsm4t(bh, svh + rv);
                ldsm4t(bl, svl + rv);
                mma16816(o[2*pr],   pah[ks], bh);
                mma16816(o[2*pr],   pah[ks], bl);
                mma16816(o[2*pr+1], pah[ks], bh+2);
                mma16816(o[2*pr+1], pah[ks], bl+2);
            }
        }
        __syncthreads();
    }

    float inv0 = 1.f / l0r, inv1 = 1.f / l1r;
    int r0 = wid*16 + (lane >> 2);
    int pc = 2 * (lane & 3);
    int rg = qbase + r0;
    int c0 = hoff + pc;
    #pragma unroll
    for (int nt = 0; nt < 8; nt++) {
        float v0 = o[nt][0] * inv0, v1 = o[nt][1] * inv0;
        float v2 = o[nt][2] * inv1, v3 = o[nt][3] * inv1;
        __nv_bfloat16 h0,l0,h1,l1,h2,l2,h3,l3;
        bsplit(v0,h0,l0); bsplit(v1,h1,l1); bsplit(v2,h2,l2); bsplit(v3,h3,l3);
        *(uint32_t*)&yh[(size_t)rg * DIM + c0 + nt*8] = bpack(h0,h1);
        *(uint32_t*)&yl[(size_t)rg * DIM + c0 + nt*8] = bpack(l0,l1);
        *(uint32_t*)&yh[(size_t)(rg+8) * DIM + c0 + nt*8] = bpack(h2,h3);
        *(uint32_t*)&yl[(size_t)(rg+8) * DIM + c0 + nt*8] = bpack(l2,l3);
    }
}

// ---------------- fused residual + LayerNorm (vectorized, +split out) ------
__global__ void ln_kernel(const float* __restrict__ x, const float* __restrict__ r,
                          const float* __restrict__ w, const float* __restrict__ b,
                          float* __restrict__ out,
                          __nv_bfloat16* __restrict__ oh, __nv_bfloat16* __restrict__ ol) {
    int row = blockIdx.x;
    int tid = threadIdx.x;
    const float4* x4 = (const float4*)(x + (size_t)row * DIM);
    const float4* r4 = (const float4*)(r + (size_t)row * DIM);
    float4 xv = x4[tid];
    float4 rv = r4[tid];
    float v0 = xv.x + rv.x, v1 = xv.y + rv.y, v2 = xv.z + rv.z, v3 = xv.w + rv.w;
    float sum = (v0 + v1) + (v2 + v3);
    __shared__ float red1[4], red2[4];
    #pragma unroll
    for (int off = 16; off; off >>= 1) sum += __shfl_xor_sync(0xffffffffu, sum, off);
    if ((tid & 31) == 0) red1[tid >> 5] = sum;
    __syncthreads();
    sum = red1[0] + red1[1] + red1[2] + red1[3];
    float mean = sum * (1.f / DIM);
    float d0 = v0 - mean, d1 = v1 - mean, d2 = v2 - mean, d3 = v3 - mean;
    float vs = (d0*d0 + d1*d1) + (d2*d2 + d3*d3);
    #pragma unroll
    for (int off = 16; off; off >>= 1) vs += __shfl_xor_sync(0xffffffffu, vs, off);
    if ((tid & 31) == 0) red2[tid >> 5] = vs;
    __syncthreads();
    vs = red2[0] + red2[1] + red2[2] + red2[3];
    float rstd = rsqrtf(vs * (1.f / DIM) + 1e-5f);
    float4 wv = ((const float4*)w)[tid];
    float4 bv = ((const float4*)b)[tid];
    float o0 = d0 * rstd * wv.x + bv.x;
    float o1 = d1 * rstd * wv.y + bv.y;
    float o2 = d2 * rstd * wv.z + bv.z;
    float o3 = d3 * rstd * wv.w + bv.w;
    ((float4*)(out + (size_t)row * DIM))[tid] = make_float4(o0, o1, o2, o3);
    __nv_bfloat16 h0,l0,h1,l1,h2,l2,h3,l3;
    bsplit(o0,h0,l0); bsplit(o1,h1,l1); bsplit(o2,h2,l2); bsplit(o3,h3,l3);
    uint2 hp = make_uint2(bpack(h0,h1), bpack(h2,h3));
    uint2 lp = make_uint2(bpack(l0,l1), bpack(l2,l3));
    ((uint2*)(oh + (size_t)row * DIM))[tid] = hp;
    ((uint2*)(ol + (size_t)row * DIM))[tid] = lp;
}

// ---------------- host ----------------
extern "C" void kernel_launch(void* const* d_in, const int* in_sizes, int n_in,
                              void* d_out, int out_size) {
    const float* features = (const float*)d_in[0];
    const float* Wq = (const float*)d_in[1];
    const float* bq = (const float*)d_in[2];
    const float* Wk = (const float*)d_in[3];
    const float* bk = (const float*)d_in[4];
    const float* Wv = (const float*)d_in[5];
    const float* bv = (const float*)d_in[6];
    const float* Wo = (const float*)d_in[7];
    const float* bo = (const float*)d_in[8];
    const float* W1 = (const float*)d_in[9];
    const float* b1 = (const float*)d_in[10];
    const float* W2 = (const float*)d_in[11];
    const float* b2 = (const float*)d_in[12];
    const float* ln1w = (const float*)d_in[13];
    const float* ln1b = (const float*)d_in[14];
    const float* ln2w = (const float*)d_in[15];
    const float* ln2b = (const float*)d_in[16];
    float* out = (float*)d_out;

    float *x, *t, *pe;
    __nv_bfloat16 *xh, *xl, *qh, *ql, *kh, *kl, *vh, *vl, *yh, *yl, *hh, *hl, *wh, *wl;
    cudaGetSymbolAddress((void**)&x, g_x);
    cudaGetSymbolAddress((void**)&t, g_t);
    cudaGetSymbolAddress((void**)&pe, g_pe);
    cudaGetSymbolAddress((void**)&xh, g_xh);
    cudaGetSymbolAddress((void**)&xl, g_xl);
    cudaGetSymbolAddress((void**)&qh, g_qh);
    cudaGetSymbolAddress((void**)&ql, g_ql);
    cudaGetSymbolAddress((void**)&kh, g_kh);
    cudaGetSymbolAddress((void**)&kl, g_kl);
    cudaGetSymbolAddress((void**)&vh, g_vh);
    cudaGetSymbolAddress((void**)&vl, g_vl);
    cudaGetSymbolAddress((void**)&yh, g_yh);
    cudaGetSymbolAddress((void**)&yl, g_yl);
    cudaGetSymbolAddress((void**)&hh, g_hh);
    cudaGetSymbolAddress((void**)&hl, g_hl);
    cudaGetSymbolAddress((void**)&wh, g_wh);
    cudaGetSymbolAddress((void**)&wl, g_wl);

    cudaFuncSetAttribute(attn_kernel, cudaFuncAttributeMaxDynamicSharedMemorySize, ATTN_SMEM);
    cudaFuncSetAttribute(qkv_gemm, cudaFuncAttributeMaxDynamicSharedMemorySize, GEMM_SMEM);
    cudaFuncSetAttribute(mma_gemm<512,0>, cudaFuncAttributeMaxDynamicSharedMemorySize, GEMM_SMEM);
    cudaFuncSetAttribute(mma_gemm<512,2>, cudaFuncAttributeMaxDynamicSharedMemorySize, GEMM_SMEM);
    cudaFuncSetAttribute(mma_gemm<256,0>, cudaFuncAttributeMaxDynamicSharedMemorySize, GEMM_SMEM);

    const size_t OQ = 0, OK = 262144, OV = 524288, OO = 786432, O1 = 1048576, O2 = 1179648;

    dim3 gW(16, 16, NL);
    dim3 gW1(16, 8, NL);
    dim3 gW2(8, 16, NL);
    transpose_split_kernel<<<gW, 256>>>(Wq, 512, 512, 512, 512, (size_t)DIM*DIM, LWSZ, wh + OQ, wl + OQ);
    transpose_split_kernel<<<gW, 256>>>(Wk, 512, 512, 512, 512, (size_t)DIM*DIM, LWSZ, wh + OK, wl + OK);
    transpose_split_kernel<<<gW, 256>>>(Wv, 512, 512, 512, 512, (size_t)DIM*DIM, LWSZ, wh + OV, wl + OV);
    transpose_split_kernel<<<gW, 256>>>(Wo, 512, 512, 512, 512, (size_t)DIM*DIM, LWSZ, wh + OO, wl + OO);
    transpose_split_kernel<<<gW1, 256>>>(W1, 512, FF, 512, FFP, (size_t)DIM*FF, LWSZ, wh + O1, wl + O1);
    transpose_split_kernel<<<gW2, 256>>>(W2, FF, 512, FFP, 512, (size_t)FF*DIM, LWSZ, wh + O2, wl + O2);

    pe_table_kernel<<<(SEQ*DIM + 255) / 256, 256>>>(pe);
    posenc_kernel<<<(TOK*DIM + 255) / 256, 256>>>(features, pe, x, xh, xl);

    dim3 gQKV(12, TOK/128);
    dim3 gD(4, TOK/128);
    dim3 gF1(2, TOK/128);
    dim3 gA(SEQ/64, NH, NB);

    for (int l = 0; l < NL; l++) {
        size_t base = (size_t)l * LWSZ;
        qkv_gemm<<<gQKV, 256, GEMM_SMEM>>>(xh, xl,
            wh+base+OQ, wl+base+OQ, wh+base+OK, wl+base+OK, wh+base+OV, wl+base+OV,
            bq + l*DIM, bk + l*DIM, bv + l*DIM,
            qh, ql, kh, kl, vh, vl);
        attn_kernel<<<gA, 128, ATTN_SMEM>>>(qh, ql, kh, kl, vh, vl, yh, yl);
        mma_gemm<512,0><<<gD, 256, GEMM_SMEM>>>(yh, yl, wh+base+OO, wl+base+OO, bo + l*DIM, t, nullptr, nullptr, DIM, DIM);
        ln_kernel<<<TOK, 128>>>(x, t, ln1w + l*DIM, ln1b + l*DIM, x, xh, xl);
        mma_gemm<512,2><<<gF1, 256, GEMM_SMEM>>>(xh, xl, wh+base+O1, wl+base+O1, b1 + l*FF, nullptr, hh, hl, FFP, FF);
        mma_gemm<256,0><<<gD, 256, GEMM_SMEM>>>(hh, hl, wh+base+O2, wl+base+O2, b2 + l*DIM, t, nullptr, nullptr, DIM, DIM);
        float* lnout = (l == NL-1) ? out : x;
        ln_kernel<<<TOK, 128>>>(x, t, ln2w + l*DIM, ln2b + l*DIM, lnout, xh, xl);
    }
}

// round 16
// speedup vs baseline: 1.0882x; 1.0079x over previous
#include <cuda_runtime.h>
#include <cuda_bf16.h>
#include <cstdint>

#define TOK 8192
#define SEQ 2048
#define DIM 512
#define NH  8
#define HDM 64
#define NL  4
#define FF  200
#define NB  4
#define FFP 256

// ---------------- device scratch (allocation-free) ----------------
__device__ float g_x[TOK*DIM];
__device__ float g_t[TOK*DIM];
__device__ float g_pe[SEQ*DIM];
__device__ __nv_bfloat16 g_xh[TOK*DIM];
__device__ __nv_bfloat16 g_xl[TOK*DIM];
__device__ __nv_bfloat16 g_qh[TOK*DIM];
__device__ __nv_bfloat16 g_ql[TOK*DIM];
__device__ __nv_bfloat16 g_kh[TOK*DIM];
__device__ __nv_bfloat16 g_kl[TOK*DIM];
__device__ __nv_bfloat16 g_vh[TOK*DIM];
__device__ __nv_bfloat16 g_vl[TOK*DIM];
__device__ __nv_bfloat16 g_yh[TOK*DIM];
__device__ __nv_bfloat16 g_yl[TOK*DIM];
__device__ __nv_bfloat16 g_hh[TOK*FFP];
__device__ __nv_bfloat16 g_hl[TOK*FFP];
#define LWSZ 1310720
__device__ __nv_bfloat16 g_wh[4*LWSZ];
__device__ __nv_bfloat16 g_wl[4*LWSZ];

// ---------------- helpers ----------------
__device__ __forceinline__ unsigned su32(const void* p) {
    return (unsigned)__cvta_generic_to_shared(p);
}
__device__ __forceinline__ void ldsm4(uint32_t* r, unsigned addr) {
    asm volatile("ldmatrix.sync.aligned.m8n8.x4.shared.b16 {%0,%1,%2,%3}, [%4];"
        : "=r"(r[0]), "=r"(r[1]), "=r"(r[2]), "=r"(r[3]) : "r"(addr));
}
__device__ __forceinline__ void ldsm4t(uint32_t* r, unsigned addr) {
    asm volatile("ldmatrix.sync.aligned.m8n8.x4.trans.shared.b16 {%0,%1,%2,%3}, [%4];"
        : "=r"(r[0]), "=r"(r[1]), "=r"(r[2]), "=r"(r[3]) : "r"(addr));
}
__device__ __forceinline__ void mma16816(float* c, const uint32_t* a, const uint32_t* b) {
    asm volatile("mma.sync.aligned.m16n8k16.row.col.f32.bf16.bf16.f32 "
        "{%0,%1,%2,%3}, {%4,%5,%6,%7}, {%8,%9}, {%0,%1,%2,%3};"
        : "+f"(c[0]), "+f"(c[1]), "+f"(c[2]), "+f"(c[3])
        : "r"(a[0]), "r"(a[1]), "r"(a[2]), "r"(a[3]), "r"(b[0]), "r"(b[1]));
}
__device__ __forceinline__ void bsplit(float v, __nv_bfloat16& h, __nv_bfloat16& l) {
    h = __float2bfloat16(v);
    l = __float2bfloat16(v - __bfloat162float(h));
}
__device__ __forceinline__ uint32_t bpack(__nv_bfloat16 a, __nv_bfloat16 b) {
    __nv_bfloat162 p = __nv_bfloat162(a, b);
    return *(uint32_t*)&p;
}
__device__ __forceinline__ void cpasync16(unsigned saddr, const void* gaddr) {
    asm volatile("cp.async.cg.shared.global [%0], [%1], 16;" :: "r"(saddr), "l"(gaddr));
}

// ---------------- fast exp2 on the FMA pipe (input <= 0) ----------------
__device__ __forceinline__ float exp2_fast(float t) {
    t = fmaxf(t, -126.0f);
    float z = t + 12582912.0f;
    int   ii = __float_as_int(z);
    float n  = z - 12582912.0f;
    float f  = t - n;
    float p  =            1.535336188319500e-4f;
    p = fmaf(p, f, 1.339887440266574e-3f);
    p = fmaf(p, f, 9.618437357674640e-3f);
    p = fmaf(p, f, 5.550332471162809e-2f);
    p = fmaf(p, f, 2.402264791363012e-1f);
    p = fmaf(p, f, 6.931472028550421e-1f);
    p = fmaf(p, f, 1.0f);
    return __int_as_float(__float_as_int(p) + (ii << 23));
}

// ---------------- positional encoding table + add ----------------
__global__ void pe_table_kernel(float* __restrict__ pe) {
    int idx = blockIdx.x * blockDim.x + threadIdx.x;
    if (idx >= SEQ*DIM) return;
    int d = idx & (DIM-1);
    int s = idx >> 9;
    int i2 = d & ~1;
    float div = expf((float)i2 * (-9.210340371976184f / (float)DIM));
    float ang = (float)s * div;
    pe[idx] = (d & 1) ? cosf(ang) : sinf(ang);
}
__global__ void posenc_kernel(const float* __restrict__ f, const float* __restrict__ pe,
                              float* __restrict__ x,
                              __nv_bfloat16* __restrict__ xh, __nv_bfloat16* __restrict__ xl) {
    int idx = blockIdx.x * blockDim.x + threadIdx.x;
    if (idx >= TOK*DIM) return;
    float v = f[idx] + pe[idx & (SEQ*DIM - 1)];
    x[idx] = v;
    __nv_bfloat16 h, l;
    bsplit(v, h, l);
    xh[idx] = h; xl[idx] = l;
}

// W [Kreal,Nreal] -> [Npad][Kpad] hi/lo, zero-padded; smem-tile transpose
__global__ void transpose_split_kernel(const float* __restrict__ W,
                                       int Kreal, int Nreal, int Kpad, int Npad,
                                       size_t wstride, size_t ostride,
                                       __nv_bfloat16* __restrict__ oh, __nv_bfloat16* __restrict__ ol) {
    __shared__ float tile[32][33];
    const float* Wl = W + (size_t)blockIdx.z * wstride;
    __nv_bfloat16* ohl = oh + (size_t)blockIdx.z * ostride;
    __nv_bfloat16* oll = ol + (size_t)blockIdx.z * ostride;
    int k0 = blockIdx.x * 32, n0 = blockIdx.y * 32;
    int tx = threadIdx.x & 31, ty = threadIdx.x >> 5;
    #pragma unroll
    for (int i = 0; i < 4; i++) {
        int k = k0 + ty + i*8;
        int n = n0 + tx;
        tile[ty + i*8][tx] = (k < Kreal && n < Nreal) ? Wl[(size_t)k * Nreal + n] : 0.f;
    }
    __syncthreads();
    #pragma unroll
    for (int i = 0; i < 4; i++) {
        int n = n0 + ty + i*8;
        int k = k0 + tx;
        float v = tile[tx][ty + i*8];
        __nv_bfloat16 h, l;
        bsplit(v, h, l);
        ohl[(size_t)n * Kpad + k] = h;
        oll[(size_t)n * Kpad + k] = l;
    }
}

// ---------------- GEMM core (64-wide chunks; round-13 proven shape) -------
#define AST_B 144
#define TILE_B (128 * AST_B)
#define GEMM_SMEM (4 * TILE_B)

template<int KTOT>
__device__ __forceinline__ void gemm_core(
    const __nv_bfloat16* Ah, const __nv_bfloat16* Al,
    const __nv_bfloat16* Bh, const __nv_bfloat16* Bl,
    int m0, int n0, char* smem, float acc[2][8][4]) {
    char* pAh = smem;
    char* pAl = smem + TILE_B;
    char* pBh = smem + 2*TILE_B;
    char* pBl = smem + 3*TILE_B;
    unsigned sAh = su32(pAh), sAl = su32(pAl), sBh = su32(pBh), sBl = su32(pBl);
    int tid = threadIdx.x;
    int wid = tid >> 5, lane = tid & 31;
    int warp_m = wid & 3, warp_n = wid >> 2;

    for (int k0 = 0; k0 < KTOT; k0 += 64) {
        #pragma unroll
        for (int it = 0; it < 4; it++) {
            int chunk = tid + it * 256;
            int r = chunk >> 3;
            int cb = (chunk & 7) * 16;
            size_t ga = ((size_t)(m0 + r) * KTOT + k0) * 2 + cb;
            size_t gb = ((size_t)(n0 + r) * KTOT + k0) * 2 + cb;
            unsigned so = (unsigned)(r * AST_B + cb);
            cpasync16(sAh + so, (const char*)Ah + ga);
            cpasync16(sAl + so, (const char*)Al + ga);
            cpasync16(sBh + so, (const char*)Bh + gb);
            cpasync16(sBl + so, (const char*)Bl + gb);
        }
        asm volatile("cp.async.commit_group;" ::: "memory");
        asm volatile("cp.async.wait_group 0;" ::: "memory");
        __syncthreads();

        #pragma unroll
        for (int ks = 0; ks < 4; ks++) {
            int colb = ks * 32;
            uint32_t ah[2][4], al[2][4];
            #pragma unroll
            for (int mt = 0; mt < 2; mt++) {
                unsigned ra = (unsigned)((warp_m*32 + mt*16 + (lane & 15)) * AST_B
                                          + colb + (lane >> 4) * 16);
                ldsm4(ah[mt], sAh + ra);
                ldsm4(al[mt], sAl + ra);
            }
            #pragma unroll
            for (int pr = 0; pr < 4; pr++) {
                unsigned rb = (unsigned)((warp_n*64 + pr*16 + (lane & 7) + ((lane >> 4) & 1) * 8) * AST_B
                                          + colb + ((lane >> 3) & 1) * 16);
                uint32_t bh[4], bl[4];
                ldsm4(bh, sBh + rb);
                ldsm4(bl, sBl + rb);
                #pragma unroll
                for (int mt = 0; mt < 2; mt++) {
                    mma16816(acc[mt][2*pr],   ah[mt], bh);
                    mma16816(acc[mt][2*pr],   ah[mt], bl);
                    mma16816(acc[mt][2*pr],   al[mt], bh);
                    mma16816(acc[mt][2*pr+1], ah[mt], bh+2);
                    mma16816(acc[mt][2*pr+1], ah[mt], bl+2);
                    mma16816(acc[mt][2*pr+1], al[mt], bh+2);
                }
            }
        }
        __syncthreads();
    }
}

template<int OUTMODE>
__device__ __forceinline__ void gemm_epi(
    float acc[2][8][4], const float* bias, float* Cf,
    __nv_bfloat16* Ch, __nv_bfloat16* Cl, int m0, int n0, int Nn, int Nreal) {
    int tid = threadIdx.x;
    int wid = tid >> 5, lane = tid & 31;
    int warp_m = wid & 3, warp_n = wid >> 2;
    #pragma unroll
    for (int mt = 0; mt < 2; mt++) {
        int r0 = m0 + warp_m*32 + mt*16 + (lane >> 2);
        #pragma unroll
        for (int nt = 0; nt < 8; nt++) {
            int c0 = n0 + warp_n*64 + nt*8 + 2*(lane & 3);
            float b0 = (c0     < Nreal) ? bias[c0]     : 0.f;
            float b1 = (c0 + 1 < Nreal) ? bias[c0 + 1] : 0.f;
            float v0 = acc[mt][nt][0] + b0;
            float v1 = acc[mt][nt][1] + b1;
            float v2 = acc[mt][nt][2] + b0;
            float v3 = acc[mt][nt][3] + b1;
            if (OUTMODE == 0) {
                *(float2*)&Cf[(size_t)r0 * Nn + c0] = make_float2(v0, v1);
                *(float2*)&Cf[(size_t)(r0 + 8) * Nn + c0] = make_float2(v2, v3);
            } else {
                if (OUTMODE == 2) {
                    v0 = (c0     < Nreal) ? fmaxf(v0, 0.f) : 0.f;
                    v1 = (c0 + 1 < Nreal) ? fmaxf(v1, 0.f) : 0.f;
                    v2 = (c0     < Nreal) ? fmaxf(v2, 0.f) : 0.f;
                    v3 = (c0 + 1 < Nreal) ? fmaxf(v3, 0.f) : 0.f;
                }
                __nv_bfloat16 h0,l0,h1,l1,h2,l2,h3,l3;
                bsplit(v0,h0,l0); bsplit(v1,h1,l1); bsplit(v2,h2,l2); bsplit(v3,h3,l3);
                *(uint32_t*)&Ch[(size_t)r0 * Nn + c0] = bpack(h0,h1);
                *(uint32_t*)&Cl[(size_t)r0 * Nn + c0] = bpack(l0,l1);
                *(uint32_t*)&Ch[(size_t)(r0 + 8) * Nn + c0] = bpack(h2,h3);
                *(uint32_t*)&Cl[(size_t)(r0 + 8) * Nn + c0] = bpack(l2,l3);
            }
        }
    }
}

template<int KTOT, int OUTMODE>
__global__ __launch_bounds__(256, 2)
void mma_gemm(const __nv_bfloat16* __restrict__ Ah, const __nv_bfloat16* __restrict__ Al,
              const __nv_bfloat16* __restrict__ Bh, const __nv_bfloat16* __restrict__ Bl,
              const float* __restrict__ bias, float* __restrict__ Cf,
              __nv_bfloat16* __restrict__ Ch, __nv_bfloat16* __restrict__ Cl,
              int Nn, int Nreal) {
    extern __shared__ char smem[];
    int m0 = blockIdx.y * 128, n0 = blockIdx.x * 128;
    float acc[2][8][4] = {};
    gemm_core<KTOT>(Ah, Al, Bh, Bl, m0, n0, smem, acc);
    gemm_epi<OUTMODE>(acc, bias, Cf, Ch, Cl, m0, n0, Nn, Nreal);
}

// fused QKV: blockIdx.x = wsel*4 + ncol
__global__ __launch_bounds__(256, 2)
void qkv_gemm(const __nv_bfloat16* __restrict__ Ah, const __nv_bfloat16* __restrict__ Al,
              const __nv_bfloat16* __restrict__ Wqh, const __nv_bfloat16* __restrict__ Wql,
              const __nv_bfloat16* __restrict__ Wkh, const __nv_bfloat16* __restrict__ Wkl,
              const __nv_bfloat16* __restrict__ Wvh, const __nv_bfloat16* __restrict__ Wvl,
              const float* __restrict__ bq, const float* __restrict__ bk, const float* __restrict__ bv,
              __nv_bfloat16* __restrict__ qh, __nv_bfloat16* __restrict__ ql,
              __nv_bfloat16* __restrict__ kh, __nv_bfloat16* __restrict__ kl,
              __nv_bfloat16* __restrict__ vh, __nv_bfloat16* __restrict__ vl) {
    extern __shared__ char smem[];
    int wsel = blockIdx.x >> 2;
    int n0 = (blockIdx.x & 3) * 128;
    int m0 = blockIdx.y * 128;
    const __nv_bfloat16* Bh = (wsel == 0) ? Wqh : (wsel == 1) ? Wkh : Wvh;
    const __nv_bfloat16* Bl = (wsel == 0) ? Wql : (wsel == 1) ? Wkl : Wvl;
    const float* bias = (wsel == 0) ? bq : (wsel == 1) ? bk : bv;
    __nv_bfloat16* Ch = (wsel == 0) ? qh : (wsel == 1) ? kh : vh;
    __nv_bfloat16* Cl = (wsel == 0) ? ql : (wsel == 1) ? kl : vl;
    float acc[2][8][4] = {};
    gemm_core<512>(Ah, Al, Bh, Bl, m0, n0, smem, acc);
    gemm_epi<1>(acc, bias, nullptr, Ch, Cl, m0, n0, DIM, DIM);
}

// ---------------- HMMA flash attention: software-pipelined (QK(t+1) ∥ softmax(t)) ----
// smem slots (bf16 elems): Q | K0 | K1 | V0 | V1, each 9216 (h at +0, l at +4608)
#define ATS 72
#define SQH 0
#define SQL 4608
#define KSLOT0 9216
#define KSLOT1 18432
#define VSLOT0 27648
#define VSLOT1 36864
#define HALF_OFF 4608
#define ATTN_SMEM (46080 * 2)   // 92,160 B -> 2 CTAs/SM

__global__ __launch_bounds__(128, 2)
void attn_kernel(const __nv_bfloat16* __restrict__ qh, const __nv_bfloat16* __restrict__ ql,
                 const __nv_bfloat16* __restrict__ kh, const __nv_bfloat16* __restrict__ kl,
                 const __nv_bfloat16* __restrict__ vh, const __nv_bfloat16* __restrict__ vl,
                 __nv_bfloat16* __restrict__ yh, __nv_bfloat16* __restrict__ yl) {
    extern __shared__ __nv_bfloat16 smb[];
    unsigned sb = su32(smb);

    int tid = threadIdx.x;
    int wid = tid >> 5, lane = tid & 31;
    int qt_blk = blockIdx.x, h = blockIdx.y, n = blockIdx.z;
    const float SCALE_LOG2E = 0.125f * 1.4426950408889634f;
    const int NT = SEQ / 64;

    int qbase = n * SEQ + qt_blk * 64;
    int hoff = h * HDM;

    // Q store
    #pragma unroll
    for (int it = 0; it < 4; it++) {
        int idx = tid + it * 128;
        int r = idx >> 3;
        int cb = (idx & 7) * 8;
        size_t ga = ((size_t)(qbase + r) * DIM + hoff + cb) * 2;
        *(uint4*)&smb[SQH + r * ATS + cb] = *(const uint4*)((const char*)qh + ga);
        *(uint4*)&smb[SQL + r * ATS + cb] = *(const uint4*)((const char*)ql + ga);
    }

    int ld_r  = tid >> 3;
    int ld_cb = (tid & 7) * 8;
    #define LOAD_K(soff, ktile) do {                                                  \
        int kb = n * SEQ + (ktile) * 64;                                              \
        _Pragma("unroll")                                                             \
        for (int it = 0; it < 4; it++) {                                              \
            int r = ld_r + it * 16;                                                   \
            size_t ga = ((size_t)(kb + r) * DIM + hoff + ld_cb) * 2;                  \
            unsigned so = sb + (unsigned)((soff) + r * ATS + ld_cb) * 2u;             \
            cpasync16(so, (const char*)kh + ga);                                      \
            cpasync16(so + HALF_OFF*2, (const char*)kl + ga);                         \
        }                                                                             \
    } while (0)
    #define LOAD_V(soff, ktile) do {                                                  \
        int kb = n * SEQ + (ktile) * 64;                                              \
        _Pragma("unroll")                                                             \
        for (int it = 0; it < 4; it++) {                                              \
            int r = ld_r + it * 16;                                                   \
            size_t ga = ((size_t)(kb + r) * DIM + hoff + ld_cb) * 2;                  \
            unsigned so = sb + (unsigned)((soff) + r * ATS + ld_cb) * 2u;             \
            cpasync16(so, (const char*)vh + ga);                                      \
            cpasync16(so + HALF_OFF*2, (const char*)vl + ga);                         \
        }                                                                             \
    } while (0)

    // prologue loads: group A = {K(0)}, group B = {V(0), K(1)}
    LOAD_K(KSLOT0, 0);
    asm volatile("cp.async.commit_group;" ::: "memory");
    LOAD_V(VSLOT0, 0);
    LOAD_K(KSLOT1, 1);
    asm volatile("cp.async.commit_group;" ::: "memory");

    __syncthreads();   // Q visible
    uint32_t qfh[4][4], qfl[4][4];
    #pragma unroll
    for (int ks = 0; ks < 4; ks++) {
        unsigned ra = (unsigned)((wid*16 + (lane & 15)) * ATS
                                  + ks*16 + (lane >> 4) * 8) * 2u;
        ldsm4(qfh[ks], sb + SQH*2 + ra);
        ldsm4(qfl[ks], sb + SQL*2 + ra);
    }

    float o[8][4] = {};
    float m0r = -1e30f, m1r = -1e30f, l0r = 0.f, l1r = 0.f;
    float sA[8][4], sB[8][4];

    // QK helper: reads K slot -> accumulates into s (s must be zeroed)
    auto qk_tile = [&](unsigned kslotB, float (&s)[8][4]) {
        #pragma unroll
        for (int ks = 0; ks < 4; ks++) {
            #pragma unroll
            for (int pr = 0; pr < 4; pr++) {
                unsigned rb = kslotB + (unsigned)((pr*16 + (lane & 7) + ((lane >> 4) & 1) * 8) * ATS
                                                   + ks*16 + ((lane >> 3) & 1) * 8) * 2u;
                uint32_t bh[4], bl[4];
                ldsm4(bh, rb);
                ldsm4(bl, rb + HALF_OFF*2);
                mma16816(s[2*pr],   qfh[ks], bh);
                mma16816(s[2*pr],   qfh[ks], bl);
                mma16816(s[2*pr],   qfl[ks], bh);
                mma16816(s[2*pr+1], qfh[ks], bh+2);
                mma16816(s[2*pr+1], qfh[ks], bl+2);
                mma16816(s[2*pr+1], qfl[ks], bh+2);
            }
        }
    };

    // wait group A (K0) done; B may be pending
    asm volatile("cp.async.wait_group 1;" ::: "memory");
    __syncthreads();
    #pragma unroll
    for (int nt = 0; nt < 8; nt++) { sA[nt][0]=0.f; sA[nt][1]=0.f; sA[nt][2]=0.f; sA[nt][3]=0.f; }
    qk_tile(sb + KSLOT0*2, sA);

    // iteration body: softmax(scur) overlapped with QK(t+1) into snxt, then PV(t)
    auto body = [&](int t, float (&scur)[8][4], float (&snxt)[8][4]) {
        asm volatile("cp.async.wait_group 0;" ::: "memory");
        __syncthreads();
        // issue next loads: K(t+2) -> K slot t&1 ; V(t+1) -> V slot (t+1)&1
        if (t + 2 < NT) LOAD_K((t & 1) ? KSLOT1 : KSLOT0, t + 2);
        if (t + 1 < NT) LOAD_V(((t + 1) & 1) ? VSLOT1 : VSLOT0, t + 1);
        asm volatile("cp.async.commit_group;" ::: "memory");

        // QK(t+1) from K slot (t+1)&1 (issued first: tensor pipe fills while softmax FMAs run)
        if (t + 1 < NT) {
            #pragma unroll
            for (int nt = 0; nt < 8; nt++) { snxt[nt][0]=0.f; snxt[nt][1]=0.f; snxt[nt][2]=0.f; snxt[nt][3]=0.f; }
            qk_tile(sb + (((t + 1) & 1) ? KSLOT1 : KSLOT0) * 2, snxt);
        }

        // softmax on scur -> pah (Ph only; Pl dropped per round-15 analysis)
        float mx0 = -1e30f, mx1 = -1e30f;
        #pragma unroll
        for (int nt = 0; nt < 8; nt++) {
            scur[nt][0] *= SCALE_LOG2E; scur[nt][1] *= SCALE_LOG2E;
            scur[nt][2] *= SCALE_LOG2E; scur[nt][3] *= SCALE_LOG2E;
            mx0 = fmaxf(mx0, fmaxf(scur[nt][0], scur[nt][1]));
            mx1 = fmaxf(mx1, fmaxf(scur[nt][2], scur[nt][3]));
        }
        mx0 = fmaxf(mx0, __shfl_xor_sync(0xffffffffu, mx0, 1));
        mx0 = fmaxf(mx0, __shfl_xor_sync(0xffffffffu, mx0, 2));
        mx1 = fmaxf(mx1, __shfl_xor_sync(0xffffffffu, mx1, 1));
        mx1 = fmaxf(mx1, __shfl_xor_sync(0xffffffffu, mx1, 2));
        float nm0 = fmaxf(m0r, mx0), nm1 = fmaxf(m1r, mx1);
        float corr0 = exp2_fast(m0r - nm0), corr1 = exp2_fast(m1r - nm1);
        m0r = nm0; m1r = nm1;
        float rs0 = 0.f, rs1 = 0.f;
        uint32_t pah[4][4];
        #pragma unroll
        for (int nt = 0; nt < 8; nt++) {
            float p0 = exp2_fast(scur[nt][0] - nm0);
            float p1 = exp2_fast(scur[nt][1] - nm0);
            float p2 = exp2_fast(scur[nt][2] - nm1);
            float p3 = exp2_fast(scur[nt][3] - nm1);
            rs0 += p0 + p1; rs1 += p2 + p3;
            o[nt][0] *= corr0; o[nt][1] *= corr0;
            o[nt][2] *= corr1; o[nt][3] *= corr1;
            __nv_bfloat16 h0 = __float2bfloat16(p0);
            __nv_bfloat16 h1 = __float2bfloat16(p1);
            __nv_bfloat16 h2 = __float2bfloat16(p2);
            __nv_bfloat16 h3 = __float2bfloat16(p3);
            int ks = nt >> 1, half = (nt & 1) * 2;
            pah[ks][half + 0] = bpack(h0,h1);
            pah[ks][half + 1] = bpack(h2,h3);
        }
        rs0 += __shfl_xor_sync(0xffffffffu, rs0, 1);
        rs0 += __shfl_xor_sync(0xffffffffu, rs0, 2);
        rs1 += __shfl_xor_sync(0xffffffffu, rs1, 1);
        rs1 += __shfl_xor_sync(0xffffffffu, rs1, 2);
        l0r = l0r * corr0 + rs0;
        l1r = l1r * corr1 + rs1;

        // PV(t): O += Ph @ (Vh + Vl), V slot t&1
        unsigned vslotB = sb + (((t & 1) ? VSLOT1 : VSLOT0)) * 2;
        #pragma unroll
        for (int ks = 0; ks < 4; ks++) {
            #pragma unroll
            for (int pr = 0; pr < 4; pr++) {
                unsigned rv = vslotB + (unsigned)((ks*16 + (lane & 7) + ((lane >> 3) & 1) * 8) * ATS
                                                   + pr*16 + ((lane >> 4) & 1) * 8) * 2u;
                uint32_t bh[4], bl[4];
                ldsm4t(bh, rv);
                ldsm4t(bl, rv + HALF_OFF*2);
                mma16816(o[2*pr],   pah[ks], bh);
                mma16816(o[2*pr],   pah[ks], bl);
                mma16816(o[2*pr+1], pah[ks], bh+2);
                mma16816(o[2*pr+1], pah[ks], bl+2);
            }
        }
    };

    for (int t = 0; t < NT; t += 2) {
        body(t, sA, sB);
        body(t + 1, sB, sA);
    }

    // epilogue
    float inv0 = 1.f / l0r, inv1 = 1.f / l1r;
    int r0 = wid*16 + (lane >> 2);
    int pc = 2 * (lane & 3);
    int rg = qbase + r0;
    int c0 = hoff + pc;
    #pragma unroll
    for (int nt = 0; nt < 8; nt++) {
        float v0 = o[nt][0] * inv0, v1 = o[nt][1] * inv0;
        float v2 = o[nt][2] * inv1, v3 = o[nt][3] * inv1;
        __nv_bfloat16 h0,l0,h1,l1,h2,l2,h3,l3;
        bsplit(v0,h0,l0); bsplit(v1,h1,l1); bsplit(v2,h2,l2); bsplit(v3,h3,l3);
        *(uint32_t*)&yh[(size_t)rg * DIM + c0 + nt*8] = bpack(h0,h1);
        *(uint32_t*)&yl[(size_t)rg * DIM + c0 + nt*8] = bpack(l0,l1);
        *(uint32_t*)&yh[(size_t)(rg+8) * DIM + c0 + nt*8] = bpack(h2,h3);
        *(uint32_t*)&yl[(size_t)(rg+8) * DIM + c0 + nt*8] = bpack(l2,l3);
    }
}

// ---------------- fused residual + LayerNorm (vectorized, +split out) ------
__global__ void ln_kernel(const float* __restrict__ x, const float* __restrict__ r,
                          const float* __restrict__ w, const float* __restrict__ b,
                          float* __restrict__ out,
                          __nv_bfloat16* __restrict__ oh, __nv_bfloat16* __restrict__ ol) {
    int row = blockIdx.x;
    int tid = threadIdx.x;
    const float4* x4 = (const float4*)(x + (size_t)row * DIM);
    const float4* r4 = (const float4*)(r + (size_t)row * DIM);
    float4 xv = x4[tid];
    float4 rv = r4[tid];
    float v0 = xv.x + rv.x, v1 = xv.y + rv.y, v2 = xv.z + rv.z, v3 = xv.w + rv.w;
    float sum = (v0 + v1) + (v2 + v3);
    __shared__ float red1[4], red2[4];
    #pragma unroll
    for (int off = 16; off; off >>= 1) sum += __shfl_xor_sync(0xffffffffu, sum, off);
    if ((tid & 31) == 0) red1[tid >> 5] = sum;
    __syncthreads();
    sum = red1[0] + red1[1] + red1[2] + red1[3];
    float mean = sum * (1.f / DIM);
    float d0 = v0 - mean, d1 = v1 - mean, d2 = v2 - mean, d3 = v3 - mean;
    float vs = (d0*d0 + d1*d1) + (d2*d2 + d3*d3);
    #pragma unroll
    for (int off = 16; off; off >>= 1) vs += __shfl_xor_sync(0xffffffffu, vs, off);
    if ((tid & 31) == 0) red2[tid >> 5] = vs;
    __syncthreads();
    vs = red2[0] + red2[1] + red2[2] + red2[3];
    float rstd = rsqrtf(vs * (1.f / DIM) + 1e-5f);
    float4 wv = ((const float4*)w)[tid];
    float4 bv = ((const float4*)b)[tid];
    float o0 = d0 * rstd * wv.x + bv.x;
    float o1 = d1 * rstd * wv.y + bv.y;
    float o2 = d2 * rstd * wv.z + bv.z;
    float o3 = d3 * rstd * wv.w + bv.w;
    ((float4*)(out + (size_t)row * DIM))[tid] = make_float4(o0, o1, o2, o3);
    __nv_bfloat16 h0,l0,h1,l1,h2,l2,h3,l3;
    bsplit(o0,h0,l0); bsplit(o1,h1,l1); bsplit(o2,h2,l2); bsplit(o3,h3,l3);
    uint2 hp = make_uint2(bpack(h0,h1), bpack(h2,h3));
    uint2 lp = make_uint2(bpack(l0,l1), bpack(l2,l3));
    ((uint2*)(oh + (size_t)row * DIM))[tid] = hp;
    ((uint2*)(ol + (size_t)row * DIM))[tid] = lp;
}

// ---------------- host ----------------
extern "C" void kernel_launch(void* const* d_in, const int* in_sizes, int n_in,
                              void* d_out, int out_size) {
    const float* features = (const float*)d_in[0];
    const float* Wq = (const float*)d_in[1];
    const float* bq = (const float*)d_in[2];
    const float* Wk = (const float*)d_in[3];
    const float* bk = (const float*)d_in[4];
    const float* Wv = (const float*)d_in[5];
    const float* bv = (const float*)d_in[6];
    const float* Wo = (const float*)d_in[7];
    const float* bo = (const float*)d_in[8];
    const float* W1 = (const float*)d_in[9];
    const float* b1 = (const float*)d_in[10];
    const float* W2 = (const float*)d_in[11];
    const float* b2 = (const float*)d_in[12];
    const float* ln1w = (const float*)d_in[13];
    const float* ln1b = (const float*)d_in[14];
    const float* ln2w = (const float*)d_in[15];
    const float* ln2b = (const float*)d_in[16];
    float* out = (float*)d_out;

    float *x, *t, *pe;
    __nv_bfloat16 *xh, *xl, *qh, *ql, *kh, *kl, *vh, *vl, *yh, *yl, *hh, *hl, *wh, *wl;
    cudaGetSymbolAddress((void**)&x, g_x);
    cudaGetSymbolAddress((void**)&t, g_t);
    cudaGetSymbolAddress((void**)&pe, g_pe);
    cudaGetSymbolAddress((void**)&xh, g_xh);
    cudaGetSymbolAddress((void**)&xl, g_xl);
    cudaGetSymbolAddress((void**)&qh, g_qh);
    cudaGetSymbolAddress((void**)&ql, g_ql);
    cudaGetSymbolAddress((void**)&kh, g_kh);
    cudaGetSymbolAddress((void**)&kl, g_kl);
    cudaGetSymbolAddress((void**)&vh, g_vh);
    cudaGetSymbolAddress((void**)&vl, g_vl);
    cudaGetSymbolAddress((void**)&yh, g_yh);
    cudaGetSymbolAddress((void**)&yl, g_yl);
    cudaGetSymbolAddress((void**)&hh, g_hh);
    cudaGetSymbolAddress((void**)&hl, g_hl);
    cudaGetSymbolAddress((void**)&wh, g_wh);
    cudaGetSymbolAddress((void**)&wl, g_wl);

    cudaFuncSetAttribute(attn_kernel, cudaFuncAttributeMaxDynamicSharedMemorySize, ATTN_SMEM);
    cudaFuncSetAttribute(qkv_gemm, cudaFuncAttributeMaxDynamicSharedMemorySize, GEMM_SMEM);
    cudaFuncSetAttribute(mma_gemm<512,0>, cudaFuncAttributeMaxDynamicSharedMemorySize, GEMM_SMEM);
    cudaFuncSetAttribute(mma_gemm<512,2>, cudaFuncAttributeMaxDynamicSharedMemorySize, GEMM_SMEM);
    cudaFuncSetAttribute(mma_gemm<256,0>, cudaFuncAttributeMaxDynamicSharedMemorySize, GEMM_SMEM);

    const size_t OQ = 0, OK = 262144, OV = 524288, OO = 786432, O1 = 1048576, O2 = 1179648;

    dim3 gW(16, 16, NL);
    dim3 gW1(16, 8, NL);
    dim3 gW2(8, 16, NL);
    transpose_split_kernel<<<gW, 256>>>(Wq, 512, 512, 512, 512, (size_t)DIM*DIM, LWSZ, wh + OQ, wl + OQ);
    transpose_split_kernel<<<gW, 256>>>(Wk, 512, 512, 512, 512, (size_t)DIM*DIM, LWSZ, wh + OK, wl + OK);
    transpose_split_kernel<<<gW, 256>>>(Wv, 512, 512, 512, 512, (size_t)DIM*DIM, LWSZ, wh + OV, wl + OV);
    transpose_split_kernel<<<gW, 256>>>(Wo, 512, 512, 512, 512, (size_t)DIM*DIM, LWSZ, wh + OO, wl + OO);
    transpose_split_kernel<<<gW1, 256>>>(W1, 512, FF, 512, FFP, (size_t)DIM*FF, LWSZ, wh + O1, wl + O1);
    transpose_split_kernel<<<gW2, 256>>>(W2, FF, 512, FFP, 512, (size_t)FF*DIM, LWSZ, wh + O2, wl + O2);

    pe_table_kernel<<<(SEQ*DIM + 255) / 256, 256>>>(pe);
    posenc_kernel<<<(TOK*DIM + 255) / 256, 256>>>(features, pe, x, xh, xl);

    dim3 gQKV(12, TOK/128);
    dim3 gD(4, TOK/128);
    dim3 gF1(2, TOK/128);
    dim3 gA(SEQ/64, NH, NB);

    for (int l = 0; l < NL; l++) {
        size_t base = (size_t)l * LWSZ;
        qkv_gemm<<<gQKV, 256, GEMM_SMEM>>>(xh, xl,
            wh+base+OQ, wl+base+OQ, wh+base+OK, wl+base+OK, wh+base+OV, wl+base+OV,
            bq + l*DIM, bk + l*DIM, bv + l*DIM,
            qh, ql, kh, kl, vh, vl);
        attn_kernel<<<gA, 128, ATTN_SMEM>>>(qh, ql, kh, kl, vh, vl, yh, yl);
        mma_gemm<512,0><<<gD, 256, GEMM_SMEM>>>(yh, yl, wh+base+OO, wl+base+OO, bo + l*DIM, t, nullptr, nullptr, DIM, DIM);
        ln_kernel<<<TOK, 128>>>(x, t, ln1w + l*DIM, ln1b + l*DIM, x, xh, xl);
        mma_gemm<512,2><<<gF1, 256, GEMM_SMEM>>>(xh, xl, wh+base+O1, wl+base+O1, b1 + l*FF, nullptr, hh, hl, FFP, FF);
        mma_gemm<256,0><<<gD, 256, GEMM_SMEM>>>(hh, hl, wh+base+O2, wl+base+O2, b2 + l*DIM, t, nullptr, nullptr, DIM, DIM);
        float* lnout = (l == NL-1) ? out : x;
        ln_kernel<<<TOK, 128>>>(x, t, ln2w + l*DIM, ln2b + l*DIM, lnout, xh, xl);
    }
}

// round 17
// speedup vs baseline: 1.2477x; 1.1466x over previous
#include <cuda_runtime.h>
#include <cuda_bf16.h>
#include <cuda_fp16.h>
#include <cstdint>

#define TOK 8192
#define SEQ 2048
#define DIM 512
#define NH  8
#define HDM 64
#define NL  4
#define FF  200
#define NB  4
#define FFP 256

// ---------------- device scratch (allocation-free) ----------------
__device__ float g_x[TOK*DIM];
__device__ float g_t[TOK*DIM];
__device__ float g_pe[SEQ*DIM];
__device__ __nv_bfloat16 g_xh[TOK*DIM];
__device__ __nv_bfloat16 g_xl[TOK*DIM];
__device__ __half g_qf[TOK*DIM];
__device__ __half g_kf[TOK*DIM];
__device__ __half g_kg[TOK*DIM];
__device__ __half g_vf[TOK*DIM];
__device__ __nv_bfloat16 g_yh[TOK*DIM];
__device__ __nv_bfloat16 g_yl[TOK*DIM];
__device__ __nv_bfloat16 g_hh[TOK*FFP];
__device__ __nv_bfloat16 g_hl[TOK*FFP];
#define LWSZ 1310720
__device__ __nv_bfloat16 g_wh[4*LWSZ];
__device__ __nv_bfloat16 g_wl[4*LWSZ];

// ---------------- helpers ----------------
__device__ __forceinline__ unsigned su32(const void* p) {
    return (unsigned)__cvta_generic_to_shared(p);
}
__device__ __forceinline__ void ldsm4(uint32_t* r, unsigned addr) {
    asm volatile("ldmatrix.sync.aligned.m8n8.x4.shared.b16 {%0,%1,%2,%3}, [%4];"
        : "=r"(r[0]), "=r"(r[1]), "=r"(r[2]), "=r"(r[3]) : "r"(addr));
}
__device__ __forceinline__ void ldsm4t(uint32_t* r, unsigned addr) {
    asm volatile("ldmatrix.sync.aligned.m8n8.x4.trans.shared.b16 {%0,%1,%2,%3}, [%4];"
        : "=r"(r[0]), "=r"(r[1]), "=r"(r[2]), "=r"(r[3]) : "r"(addr));
}
__device__ __forceinline__ void mma16816(float* c, const uint32_t* a, const uint32_t* b) {
    asm volatile("mma.sync.aligned.m16n8k16.row.col.f32.bf16.bf16.f32 "
        "{%0,%1,%2,%3}, {%4,%5,%6,%7}, {%8,%9}, {%0,%1,%2,%3};"
        : "+f"(c[0]), "+f"(c[1]), "+f"(c[2]), "+f"(c[3])
        : "r"(a[0]), "r"(a[1]), "r"(a[2]), "r"(a[3]), "r"(b[0]), "r"(b[1]));
}
__device__ __forceinline__ void mma16816h(float* c, const uint32_t* a, const uint32_t* b) {
    asm volatile("mma.sync.aligned.m16n8k16.row.col.f32.f16.f16.f32 "
        "{%0,%1,%2,%3}, {%4,%5,%6,%7}, {%8,%9}, {%0,%1,%2,%3};"
        : "+f"(c[0]), "+f"(c[1]), "+f"(c[2]), "+f"(c[3])
        : "r"(a[0]), "r"(a[1]), "r"(a[2]), "r"(a[3]), "r"(b[0]), "r"(b[1]));
}
__device__ __forceinline__ void bsplit(float v, __nv_bfloat16& h, __nv_bfloat16& l) {
    h = __float2bfloat16(v);
    l = __float2bfloat16(v - __bfloat162float(h));
}
__device__ __forceinline__ uint32_t bpack(__nv_bfloat16 a, __nv_bfloat16 b) {
    __nv_bfloat162 p = __nv_bfloat162(a, b);
    return *(uint32_t*)&p;
}
__device__ __forceinline__ uint32_t hpack(__half a, __half b) {
    __half2 p = __half2(a, b);
    return *(uint32_t*)&p;
}
__device__ __forceinline__ void cpasync16(unsigned saddr, const void* gaddr) {
    asm volatile("cp.async.cg.shared.global [%0], [%1], 16;" :: "r"(saddr), "l"(gaddr));
}

// ---------------- fast exp2 on the FMA pipe (input <= 0) ----------------
__device__ __forceinline__ float exp2_fast(float t) {
    t = fmaxf(t, -126.0f);
    float z = t + 12582912.0f;
    int   ii = __float_as_int(z);
    float n  = z - 12582912.0f;
    float f  = t - n;
    float p  =            1.535336188319500e-4f;
    p = fmaf(p, f, 1.339887440266574e-3f);
    p = fmaf(p, f, 9.618437357674640e-3f);
    p = fmaf(p, f, 5.550332471162809e-2f);
    p = fmaf(p, f, 2.402264791363012e-1f);
    p = fmaf(p, f, 6.931472028550421e-1f);
    p = fmaf(p, f, 1.0f);
    return __int_as_float(__float_as_int(p) + (ii << 23));
}

// ---------------- positional encoding table + add ----------------
__global__ void pe_table_kernel(float* __restrict__ pe) {
    int idx = blockIdx.x * blockDim.x + threadIdx.x;
    if (idx >= SEQ*DIM) return;
    int d = idx & (DIM-1);
    int s = idx >> 9;
    int i2 = d & ~1;
    float div = expf((float)i2 * (-9.210340371976184f / (float)DIM));
    float ang = (float)s * div;
    pe[idx] = (d & 1) ? cosf(ang) : sinf(ang);
}
__global__ void posenc_kernel(const float* __restrict__ f, const float* __restrict__ pe,
                              float* __restrict__ x,
                              __nv_bfloat16* __restrict__ xh, __nv_bfloat16* __restrict__ xl) {
    int idx = blockIdx.x * blockDim.x + threadIdx.x;
    if (idx >= TOK*DIM) return;
    float v = f[idx] + pe[idx & (SEQ*DIM - 1)];
    x[idx] = v;
    __nv_bfloat16 h, l;
    bsplit(v, h, l);
    xh[idx] = h; xl[idx] = l;
}

// W [Kreal,Nreal] -> [Npad][Kpad] hi/lo, zero-padded; smem-tile transpose
__global__ void transpose_split_kernel(const float* __restrict__ W,
                                       int Kreal, int Nreal, int Kpad, int Npad,
                                       size_t wstride, size_t ostride,
                                       __nv_bfloat16* __restrict__ oh, __nv_bfloat16* __restrict__ ol) {
    __shared__ float tile[32][33];
    const float* Wl = W + (size_t)blockIdx.z * wstride;
    __nv_bfloat16* ohl = oh + (size_t)blockIdx.z * ostride;
    __nv_bfloat16* oll = ol + (size_t)blockIdx.z * ostride;
    int k0 = blockIdx.x * 32, n0 = blockIdx.y * 32;
    int tx = threadIdx.x & 31, ty = threadIdx.x >> 5;
    #pragma unroll
    for (int i = 0; i < 4; i++) {
        int k = k0 + ty + i*8;
        int n = n0 + tx;
        tile[ty + i*8][tx] = (k < Kreal && n < Nreal) ? Wl[(size_t)k * Nreal + n] : 0.f;
    }
    __syncthreads();
    #pragma unroll
    for (int i = 0; i < 4; i++) {
        int n = n0 + ty + i*8;
        int k = k0 + tx;
        float v = tile[tx][ty + i*8];
        __nv_bfloat16 h, l;
        bsplit(v, h, l);
        ohl[(size_t)n * Kpad + k] = h;
        oll[(size_t)n * Kpad + k] = l;
    }
}

// ---------------- GEMM core (64-wide chunks; bf16 3-term) -----------------
#define AST_B 144
#define TILE_B (128 * AST_B)
#define GEMM_SMEM (4 * TILE_B)

template<int KTOT>
__device__ __forceinline__ void gemm_core(
    const __nv_bfloat16* Ah, const __nv_bfloat16* Al,
    const __nv_bfloat16* Bh, const __nv_bfloat16* Bl,
    int m0, int n0, char* smem, float acc[2][8][4]) {
    char* pAh = smem;
    char* pAl = smem + TILE_B;
    char* pBh = smem + 2*TILE_B;
    char* pBl = smem + 3*TILE_B;
    unsigned sAh = su32(pAh), sAl = su32(pAl), sBh = su32(pBh), sBl = su32(pBl);
    int tid = threadIdx.x;
    int wid = tid >> 5, lane = tid & 31;
    int warp_m = wid & 3, warp_n = wid >> 2;

    for (int k0 = 0; k0 < KTOT; k0 += 64) {
        #pragma unroll
        for (int it = 0; it < 4; it++) {
            int chunk = tid + it * 256;
            int r = chunk >> 3;
            int cb = (chunk & 7) * 16;
            size_t ga = ((size_t)(m0 + r) * KTOT + k0) * 2 + cb;
            size_t gb = ((size_t)(n0 + r) * KTOT + k0) * 2 + cb;
            unsigned so = (unsigned)(r * AST_B + cb);
            cpasync16(sAh + so, (const char*)Ah + ga);
            cpasync16(sAl + so, (const char*)Al + ga);
            cpasync16(sBh + so, (const char*)Bh + gb);
            cpasync16(sBl + so, (const char*)Bl + gb);
        }
        asm volatile("cp.async.commit_group;" ::: "memory");
        asm volatile("cp.async.wait_group 0;" ::: "memory");
        __syncthreads();

        #pragma unroll
        for (int ks = 0; ks < 4; ks++) {
            int colb = ks * 32;
            uint32_t ah[2][4], al[2][4];
            #pragma unroll
            for (int mt = 0; mt < 2; mt++) {
                unsigned ra = (unsigned)((warp_m*32 + mt*16 + (lane & 15)) * AST_B
                                          + colb + (lane >> 4) * 16);
                ldsm4(ah[mt], sAh + ra);
                ldsm4(al[mt], sAl + ra);
            }
            #pragma unroll
            for (int pr = 0; pr < 4; pr++) {
                unsigned rb = (unsigned)((warp_n*64 + pr*16 + (lane & 7) + ((lane >> 4) & 1) * 8) * AST_B
                                          + colb + ((lane >> 3) & 1) * 16);
                uint32_t bh[4], bl[4];
                ldsm4(bh, sBh + rb);
                ldsm4(bl, sBl + rb);
                #pragma unroll
                for (int mt = 0; mt < 2; mt++) {
                    mma16816(acc[mt][2*pr],   ah[mt], bh);
                    mma16816(acc[mt][2*pr],   ah[mt], bl);
                    mma16816(acc[mt][2*pr],   al[mt], bh);
                    mma16816(acc[mt][2*pr+1], ah[mt], bh+2);
                    mma16816(acc[mt][2*pr+1], ah[mt], bl+2);
                    mma16816(acc[mt][2*pr+1], al[mt], bh+2);
                }
            }
        }
        __syncthreads();
    }
}

template<int OUTMODE>
__device__ __forceinline__ void gemm_epi(
    float acc[2][8][4], const float* bias, float* Cf,
    __nv_bfloat16* Ch, __nv_bfloat16* Cl, int m0, int n0, int Nn, int Nreal) {
    int tid = threadIdx.x;
    int wid = tid >> 5, lane = tid & 31;
    int warp_m = wid & 3, warp_n = wid >> 2;
    #pragma unroll
    for (int mt = 0; mt < 2; mt++) {
        int r0 = m0 + warp_m*32 + mt*16 + (lane >> 2);
        #pragma unroll
        for (int nt = 0; nt < 8; nt++) {
            int c0 = n0 + warp_n*64 + nt*8 + 2*(lane & 3);
            float b0 = (c0     < Nreal) ? bias[c0]     : 0.f;
            float b1 = (c0 + 1 < Nreal) ? bias[c0 + 1] : 0.f;
            float v0 = acc[mt][nt][0] + b0;
            float v1 = acc[mt][nt][1] + b1;
            float v2 = acc[mt][nt][2] + b0;
            float v3 = acc[mt][nt][3] + b1;
            if (OUTMODE == 0) {
                *(float2*)&Cf[(size_t)r0 * Nn + c0] = make_float2(v0, v1);
                *(float2*)&Cf[(size_t)(r0 + 8) * Nn + c0] = make_float2(v2, v3);
            } else {
                if (OUTMODE == 2) {
                    v0 = (c0     < Nreal) ? fmaxf(v0, 0.f) : 0.f;
                    v1 = (c0 + 1 < Nreal) ? fmaxf(v1, 0.f) : 0.f;
                    v2 = (c0     < Nreal) ? fmaxf(v2, 0.f) : 0.f;
                    v3 = (c0 + 1 < Nreal) ? fmaxf(v3, 0.f) : 0.f;
                }
                __nv_bfloat16 h0,l0,h1,l1,h2,l2,h3,l3;
                bsplit(v0,h0,l0); bsplit(v1,h1,l1); bsplit(v2,h2,l2); bsplit(v3,h3,l3);
                *(uint32_t*)&Ch[(size_t)r0 * Nn + c0] = bpack(h0,h1);
                *(uint32_t*)&Cl[(size_t)r0 * Nn + c0] = bpack(l0,l1);
                *(uint32_t*)&Ch[(size_t)(r0 + 8) * Nn + c0] = bpack(h2,h3);
                *(uint32_t*)&Cl[(size_t)(r0 + 8) * Nn + c0] = bpack(l2,l3);
            }
        }
    }
}

template<int KTOT, int OUTMODE>
__global__ __launch_bounds__(256, 2)
void mma_gemm(const __nv_bfloat16* __restrict__ Ah, const __nv_bfloat16* __restrict__ Al,
              const __nv_bfloat16* __restrict__ Bh, const __nv_bfloat16* __restrict__ Bl,
              const float* __restrict__ bias, float* __restrict__ Cf,
              __nv_bfloat16* __restrict__ Ch, __nv_bfloat16* __restrict__ Cl,
              int Nn, int Nreal) {
    extern __shared__ char smem[];
    int m0 = blockIdx.y * 128, n0 = blockIdx.x * 128;
    float acc[2][8][4] = {};
    gemm_core<KTOT>(Ah, Al, Bh, Bl, m0, n0, smem, acc);
    gemm_epi<OUTMODE>(acc, bias, Cf, Ch, Cl, m0, n0, Nn, Nreal);
}

// fused QKV: blockIdx.x = wsel*4 + ncol; fp16 outputs (Q:h, K:h+l, V:h)
__global__ __launch_bounds__(256, 2)
void qkv_gemm(const __nv_bfloat16* __restrict__ Ah, const __nv_bfloat16* __restrict__ Al,
              const __nv_bfloat16* __restrict__ Wqh, const __nv_bfloat16* __restrict__ Wql,
              const __nv_bfloat16* __restrict__ Wkh, const __nv_bfloat16* __restrict__ Wkl,
              const __nv_bfloat16* __restrict__ Wvh, const __nv_bfloat16* __restrict__ Wvl,
              const float* __restrict__ bq, const float* __restrict__ bk, const float* __restrict__ bv,
              __half* __restrict__ qf, __half* __restrict__ kf,
              __half* __restrict__ kg, __half* __restrict__ vf) {
    extern __shared__ char smem[];
    int wsel = blockIdx.x >> 2;
    int n0 = (blockIdx.x & 3) * 128;
    int m0 = blockIdx.y * 128;
    const __nv_bfloat16* Bh = (wsel == 0) ? Wqh : (wsel == 1) ? Wkh : Wvh;
    const __nv_bfloat16* Bl = (wsel == 0) ? Wql : (wsel == 1) ? Wkl : Wvl;
    const float* bias = (wsel == 0) ? bq : (wsel == 1) ? bk : bv;
    __half* Ch = (wsel == 0) ? qf : (wsel == 1) ? kf : vf;
    float acc[2][8][4] = {};
    gemm_core<512>(Ah, Al, Bh, Bl, m0, n0, smem, acc);

    int tid = threadIdx.x;
    int wid = tid >> 5, lane = tid & 31;
    int warp_m = wid & 3, warp_n = wid >> 2;
    #pragma unroll
    for (int mt = 0; mt < 2; mt++) {
        int r0 = m0 + warp_m*32 + mt*16 + (lane >> 2);
        #pragma unroll
        for (int nt = 0; nt < 8; nt++) {
            int c0 = n0 + warp_n*64 + nt*8 + 2*(lane & 3);
            float b0 = bias[c0], b1 = bias[c0 + 1];
            float v0 = acc[mt][nt][0] + b0;
            float v1 = acc[mt][nt][1] + b1;
            float v2 = acc[mt][nt][2] + b0;
            float v3 = acc[mt][nt][3] + b1;
            __half h0 = __float2half_rn(v0), h1 = __float2half_rn(v1);
            __half h2 = __float2half_rn(v2), h3 = __float2half_rn(v3);
            *(uint32_t*)&Ch[(size_t)r0 * DIM + c0] = hpack(h0,h1);
            *(uint32_t*)&Ch[(size_t)(r0 + 8) * DIM + c0] = hpack(h2,h3);
            if (wsel == 1) {
                __half l0 = __float2half_rn(v0 - __half2float(h0));
                __half l1 = __float2half_rn(v1 - __half2float(h1));
                __half l2 = __float2half_rn(v2 - __half2float(h2));
                __half l3 = __float2half_rn(v3 - __half2float(h3));
                *(uint32_t*)&kg[(size_t)r0 * DIM + c0] = hpack(l0,l1);
                *(uint32_t*)&kg[(size_t)(r0 + 8) * DIM + c0] = hpack(l2,l3);
            }
        }
    }
}

// ---------------- fp16 flash attention: QK 2-term, PV 1-term --------------
// smem (half elems): Q(4608) | K0(9216: h,l) | K1(9216) | V0(4608) | V1(4608)
#define ATS 72
#define SQF 0
#define KSLOT0 4608
#define KSLOT1 13824
#define VSLOT0 23040
#define VSLOT1 27648
#define HALF_OFF 4608
#define ATTN_SMEM (32256 * 2)   // 64,512 B -> 2 CTAs/SM

__global__ __launch_bounds__(128, 2)
void attn_kernel(const __half* __restrict__ qf, const __half* __restrict__ kf,
                 const __half* __restrict__ kg, const __half* __restrict__ vf,
                 __nv_bfloat16* __restrict__ yh, __nv_bfloat16* __restrict__ yl) {
    extern __shared__ __half smh[];
    unsigned sb = su32(smh);

    int tid = threadIdx.x;
    int wid = tid >> 5, lane = tid & 31;
    int qt_blk = blockIdx.x, h = blockIdx.y, n = blockIdx.z;
    const float SCALE_LOG2E = 0.125f * 1.4426950408889634f;
    const int NT = SEQ / 64;

    int qbase = n * SEQ + qt_blk * 64;
    int hoff = h * HDM;

    // Q store (h only)
    #pragma unroll
    for (int it = 0; it < 4; it++) {
        int idx = tid + it * 128;
        int r = idx >> 3;
        int cb = (idx & 7) * 8;
        size_t ga = ((size_t)(qbase + r) * DIM + hoff + cb) * 2;
        *(uint4*)&smh[SQF + r * ATS + cb] = *(const uint4*)((const char*)qf + ga);
    }

    int ld_r  = tid >> 3;
    int ld_cb = (tid & 7) * 8;
    #define LOAD_K(soff, ktile) do {                                                  \
        int kb = n * SEQ + (ktile) * 64;                                              \
        _Pragma("unroll")                                                             \
        for (int it = 0; it < 4; it++) {                                              \
            int r = ld_r + it * 16;                                                   \
            size_t ga = ((size_t)(kb + r) * DIM + hoff + ld_cb) * 2;                  \
            unsigned so = sb + (unsigned)((soff) + r * ATS + ld_cb) * 2u;             \
            cpasync16(so, (const char*)kf + ga);                                      \
            cpasync16(so + HALF_OFF*2, (const char*)kg + ga);                         \
        }                                                                             \
    } while (0)
    #define LOAD_V(soff, ktile) do {                                                  \
        int kb = n * SEQ + (ktile) * 64;                                              \
        _Pragma("unroll")                                                             \
        for (int it = 0; it < 4; it++) {                                              \
            int r = ld_r + it * 16;                                                   \
            size_t ga = ((size_t)(kb + r) * DIM + hoff + ld_cb) * 2;                  \
            unsigned so = sb + (unsigned)((soff) + r * ATS + ld_cb) * 2u;             \
            cpasync16(so, (const char*)vf + ga);                                      \
        }                                                                             \
    } while (0)

    LOAD_K(KSLOT0, 0);
    asm volatile("cp.async.commit_group;" ::: "memory");
    LOAD_V(VSLOT0, 0);
    LOAD_K(KSLOT1, 1);
    asm volatile("cp.async.commit_group;" ::: "memory");

    __syncthreads();   // Q visible
    uint32_t qfr[4][4];
    #pragma unroll
    for (int ks = 0; ks < 4; ks++) {
        unsigned ra = (unsigned)((wid*16 + (lane & 15)) * ATS
                                  + ks*16 + (lane >> 4) * 8) * 2u;
        ldsm4(qfr[ks], sb + SQF*2 + ra);
    }

    float o[8][4] = {};
    float m0r = -1e30f, m1r = -1e30f, l0r = 0.f, l1r = 0.f;
    float sA[8][4], sB[8][4];

    auto qk_tile = [&](unsigned kslotB, float (&s)[8][4]) {
        #pragma unroll
        for (int ks = 0; ks < 4; ks++) {
            #pragma unroll
            for (int pr = 0; pr < 4; pr++) {
                unsigned rb = kslotB + (unsigned)((pr*16 + (lane & 7) + ((lane >> 4) & 1) * 8) * ATS
                                                   + ks*16 + ((lane >> 3) & 1) * 8) * 2u;
                uint32_t bh[4], bl[4];
                ldsm4(bh, rb);
                ldsm4(bl, rb + HALF_OFF*2);
                mma16816h(s[2*pr],   qfr[ks], bh);
                mma16816h(s[2*pr],   qfr[ks], bl);
                mma16816h(s[2*pr+1], qfr[ks], bh+2);
                mma16816h(s[2*pr+1], qfr[ks], bl+2);
            }
        }
    };

    asm volatile("cp.async.wait_group 1;" ::: "memory");
    __syncthreads();
    #pragma unroll
    for (int nt = 0; nt < 8; nt++) { sA[nt][0]=0.f; sA[nt][1]=0.f; sA[nt][2]=0.f; sA[nt][3]=0.f; }
    qk_tile(sb + KSLOT0*2, sA);

    auto body = [&](int t, float (&scur)[8][4], float (&snxt)[8][4]) {
        asm volatile("cp.async.wait_group 0;" ::: "memory");
        __syncthreads();
        if (t + 2 < NT) LOAD_K((t & 1) ? KSLOT1 : KSLOT0, t + 2);
        if (t + 1 < NT) LOAD_V(((t + 1) & 1) ? VSLOT1 : VSLOT0, t + 1);
        asm volatile("cp.async.commit_group;" ::: "memory");

        if (t + 1 < NT) {
            #pragma unroll
            for (int nt = 0; nt < 8; nt++) { snxt[nt][0]=0.f; snxt[nt][1]=0.f; snxt[nt][2]=0.f; snxt[nt][3]=0.f; }
            qk_tile(sb + (((t + 1) & 1) ? KSLOT1 : KSLOT0) * 2, snxt);
        }

        float mx0 = -1e30f, mx1 = -1e30f;
        #pragma unroll
        for (int nt = 0; nt < 8; nt++) {
            scur[nt][0] *= SCALE_LOG2E; scur[nt][1] *= SCALE_LOG2E;
            scur[nt][2] *= SCALE_LOG2E; scur[nt][3] *= SCALE_LOG2E;
            mx0 = fmaxf(mx0, fmaxf(scur[nt][0], scur[nt][1]));
            mx1 = fmaxf(mx1, fmaxf(scur[nt][2], scur[nt][3]));
        }
        mx0 = fmaxf(mx0, __shfl_xor_sync(0xffffffffu, mx0, 1));
        mx0 = fmaxf(mx0, __shfl_xor_sync(0xffffffffu, mx0, 2));
        mx1 = fmaxf(mx1, __shfl_xor_sync(0xffffffffu, mx1, 1));
        mx1 = fmaxf(mx1, __shfl_xor_sync(0xffffffffu, mx1, 2));
        float nm0 = fmaxf(m0r, mx0), nm1 = fmaxf(m1r, mx1);
        float corr0 = exp2_fast(m0r - nm0), corr1 = exp2_fast(m1r - nm1);
        m0r = nm0; m1r = nm1;
        float rs0 = 0.f, rs1 = 0.f;
        uint32_t pah[4][4];
        #pragma unroll
        for (int nt = 0; nt < 8; nt++) {
            float p0 = exp2_fast(scur[nt][0] - nm0);
            float p1 = exp2_fast(scur[nt][1] - nm0);
            float p2 = exp2_fast(scur[nt][2] - nm1);
            float p3 = exp2_fast(scur[nt][3] - nm1);
            rs0 += p0 + p1; rs1 += p2 + p3;
            o[nt][0] *= corr0; o[nt][1] *= corr0;
            o[nt][2] *= corr1; o[nt][3] *= corr1;
            __half h0 = __float2half_rn(p0);
            __half h1 = __float2half_rn(p1);
            __half h2 = __float2half_rn(p2);
            __half h3 = __float2half_rn(p3);
            int ks = nt >> 1, half = (nt & 1) * 2;
            pah[ks][half + 0] = hpack(h0,h1);
            pah[ks][half + 1] = hpack(h2,h3);
        }
        rs0 += __shfl_xor_sync(0xffffffffu, rs0, 1);
        rs0 += __shfl_xor_sync(0xffffffffu, rs0, 2);
        rs1 += __shfl_xor_sync(0xffffffffu, rs1, 1);
        rs1 += __shfl_xor_sync(0xffffffffu, rs1, 2);
        l0r = l0r * corr0 + rs0;
        l1r = l1r * corr1 + rs1;

        // PV(t): O += Ph @ Vh, V slot t&1
        unsigned vslotB = sb + (((t & 1) ? VSLOT1 : VSLOT0)) * 2;
        #pragma unroll
        for (int ks = 0; ks < 4; ks++) {
            #pragma unroll
            for (int pr = 0; pr < 4; pr++) {
                unsigned rv = vslotB + (unsigned)((ks*16 + (lane & 7) + ((lane >> 3) & 1) * 8) * ATS
                                                   + pr*16 + ((lane >> 4) & 1) * 8) * 2u;
                uint32_t bh[4];
                ldsm4t(bh, rv);
                mma16816h(o[2*pr],   pah[ks], bh);
                mma16816h(o[2*pr+1], pah[ks], bh+2);
            }
        }
    };

    for (int t = 0; t < NT; t += 2) {
        body(t, sA, sB);
        body(t + 1, sB, sA);
    }

    // epilogue: bf16-split y for the Wo GEMM
    float inv0 = 1.f / l0r, inv1 = 1.f / l1r;
    int r0 = wid*16 + (lane >> 2);
    int pc = 2 * (lane & 3);
    int rg = qbase + r0;
    int c0 = hoff + pc;
    #pragma unroll
    for (int nt = 0; nt < 8; nt++) {
        float v0 = o[nt][0] * inv0, v1 = o[nt][1] * inv0;
        float v2 = o[nt][2] * inv1, v3 = o[nt][3] * inv1;
        __nv_bfloat16 h0,l0,h1,l1,h2,l2,h3,l3;
        bsplit(v0,h0,l0); bsplit(v1,h1,l1); bsplit(v2,h2,l2); bsplit(v3,h3,l3);
        *(uint32_t*)&yh[(size_t)rg * DIM + c0 + nt*8] = bpack(h0,h1);
        *(uint32_t*)&yl[(size_t)rg * DIM + c0 + nt*8] = bpack(l0,l1);
        *(uint32_t*)&yh[(size_t)(rg+8) * DIM + c0 + nt*8] = bpack(h2,h3);
        *(uint32_t*)&yl[(size_t)(rg+8) * DIM + c0 + nt*8] = bpack(l2,l3);
    }
}

// ---------------- fused residual + LayerNorm (vectorized, +split out) ------
__global__ void ln_kernel(const float* __restrict__ x, const float* __restrict__ r,
                          const float* __restrict__ w, const float* __restrict__ b,
                          float* __restrict__ out,
                          __nv_bfloat16* __restrict__ oh, __nv_bfloat16* __restrict__ ol) {
    int row = blockIdx.x;
    int tid = threadIdx.x;
    const float4* x4 = (const float4*)(x + (size_t)row * DIM);
    const float4* r4 = (const float4*)(r + (size_t)row * DIM);
    float4 xv = x4[tid];
    float4 rv = r4[tid];
    float v0 = xv.x + rv.x, v1 = xv.y + rv.y, v2 = xv.z + rv.z, v3 = xv.w + rv.w;
    float sum = (v0 + v1) + (v2 + v3);
    __shared__ float red1[4], red2[4];
    #pragma unroll
    for (int off = 16; off; off >>= 1) sum += __shfl_xor_sync(0xffffffffu, sum, off);
    if ((tid & 31) == 0) red1[tid >> 5] = sum;
    __syncthreads();
    sum = red1[0] + red1[1] + red1[2] + red1[3];
    float mean = sum * (1.f / DIM);
    float d0 = v0 - mean, d1 = v1 - mean, d2 = v2 - mean, d3 = v3 - mean;
    float vs = (d0*d0 + d1*d1) + (d2*d2 + d3*d3);
    #pragma unroll
    for (int off = 16; off; off >>= 1) vs += __shfl_xor_sync(0xffffffffu, vs, off);
    if ((tid & 31) == 0) red2[tid >> 5] = vs;
    __syncthreads();
    vs = red2[0] + red2[1] + red2[2] + red2[3];
    float rstd = rsqrtf(vs * (1.f / DIM) + 1e-5f);
    float4 wv = ((const float4*)w)[tid];
    float4 bv = ((const float4*)b)[tid];
    float o0 = d0 * rstd * wv.x + bv.x;
    float o1 = d1 * rstd * wv.y + bv.y;
    float o2 = d2 * rstd * wv.z + bv.z;
    float o3 = d3 * rstd * wv.w + bv.w;
    ((float4*)(out + (size_t)row * DIM))[tid] = make_float4(o0, o1, o2, o3);
    __nv_bfloat16 h0,l0,h1,l1,h2,l2,h3,l3;
    bsplit(o0,h0,l0); bsplit(o1,h1,l1); bsplit(o2,h2,l2); bsplit(o3,h3,l3);
    uint2 hp = make_uint2(bpack(h0,h1), bpack(h2,h3));
    uint2 lp = make_uint2(bpack(l0,l1), bpack(l2,l3));
    ((uint2*)(oh + (size_t)row * DIM))[tid] = hp;
    ((uint2*)(ol + (size_t)row * DIM))[tid] = lp;
}

// ---------------- host ----------------
extern "C" void kernel_launch(void* const* d_in, const int* in_sizes, int n_in,
                              void* d_out, int out_size) {
    const float* features = (const float*)d_in[0];
    const float* Wq = (const float*)d_in[1];
    const float* bq = (const float*)d_in[2];
    const float* Wk = (const float*)d_in[3];
    const float* bk = (const float*)d_in[4];
    const float* Wv = (const float*)d_in[5];
    const float* bv = (const float*)d_in[6];
    const float* Wo = (const float*)d_in[7];
    const float* bo = (const float*)d_in[8];
    const float* W1 = (const float*)d_in[9];
    const float* b1 = (const float*)d_in[10];
    const float* W2 = (const float*)d_in[11];
    const float* b2 = (const float*)d_in[12];
    const float* ln1w = (const float*)d_in[13];
    const float* ln1b = (const float*)d_in[14];
    const float* ln2w = (const float*)d_in[15];
    const float* ln2b = (const float*)d_in[16];
    float* out = (float*)d_out;

    float *x, *t, *pe;
    __nv_bfloat16 *xh, *xl, *yh, *yl, *hh, *hl, *wh, *wl;
    __half *qf, *kf, *kg, *vf;
    cudaGetSymbolAddress((void**)&x, g_x);
    cudaGetSymbolAddress((void**)&t, g_t);
    cudaGetSymbolAddress((void**)&pe, g_pe);
    cudaGetSymbolAddress((void**)&xh, g_xh);
    cudaGetSymbolAddress((void**)&xl, g_xl);
    cudaGetSymbolAddress((void**)&qf, g_qf);
    cudaGetSymbolAddress((void**)&kf, g_kf);
    cudaGetSymbolAddress((void**)&kg, g_kg);
    cudaGetSymbolAddress((void**)&vf, g_vf);
    cudaGetSymbolAddress((void**)&yh, g_yh);
    cudaGetSymbolAddress((void**)&yl, g_yl);
    cudaGetSymbolAddress((void**)&hh, g_hh);
    cudaGetSymbolAddress((void**)&hl, g_hl);
    cudaGetSymbolAddress((void**)&wh, g_wh);
    cudaGetSymbolAddress((void**)&wl, g_wl);

    cudaFuncSetAttribute(attn_kernel, cudaFuncAttributeMaxDynamicSharedMemorySize, ATTN_SMEM);
    cudaFuncSetAttribute(qkv_gemm, cudaFuncAttributeMaxDynamicSharedMemorySize, GEMM_SMEM);
    cudaFuncSetAttribute(mma_gemm<512,0>, cudaFuncAttributeMaxDynamicSharedMemorySize, GEMM_SMEM);
    cudaFuncSetAttribute(mma_gemm<512,2>, cudaFuncAttributeMaxDynamicSharedMemorySize, GEMM_SMEM);
    cudaFuncSetAttribute(mma_gemm<256,0>, cudaFuncAttributeMaxDynamicSharedMemorySize, GEMM_SMEM);

    const size_t OQ = 0, OK = 262144, OV = 524288, OO = 786432, O1 = 1048576, O2 = 1179648;

    dim3 gW(16, 16, NL);
    dim3 gW1(16, 8, NL);
    dim3 gW2(8, 16, NL);
    transpose_split_kernel<<<gW, 256>>>(Wq, 512, 512, 512, 512, (size_t)DIM*DIM, LWSZ, wh + OQ, wl + OQ);
    transpose_split_kernel<<<gW, 256>>>(Wk, 512, 512, 512, 512, (size_t)DIM*DIM, LWSZ, wh + OK, wl + OK);
    transpose_split_kernel<<<gW, 256>>>(Wv, 512, 512, 512, 512, (size_t)DIM*DIM, LWSZ, wh + OV, wl + OV);
    transpose_split_kernel<<<gW, 256>>>(Wo, 512, 512, 512, 512, (size_t)DIM*DIM, LWSZ, wh + OO, wl + OO);
    transpose_split_kernel<<<gW1, 256>>>(W1, 512, FF, 512, FFP, (size_t)DIM*FF, LWSZ, wh + O1, wl + O1);
    transpose_split_kernel<<<gW2, 256>>>(W2, FF, 512, FFP, 512, (size_t)FF*DIM, LWSZ, wh + O2, wl + O2);

    pe_table_kernel<<<(SEQ*DIM + 255) / 256, 256>>>(pe);
    posenc_kernel<<<(TOK*DIM + 255) / 256, 256>>>(features, pe, x, xh, xl);

    dim3 gQKV(12, TOK/128);
    dim3 gD(4, TOK/128);
    dim3 gF1(2, TOK/128);
    dim3 gA(SEQ/64, NH, NB);

    for (int l = 0; l < NL; l++) {
        size_t base = (size_t)l * LWSZ;
        qkv_gemm<<<gQKV, 256, GEMM_SMEM>>>(xh, xl,
            wh+base+OQ, wl+base+OQ, wh+base+OK, wl+base+OK, wh+base+OV, wl+base+OV,
            bq + l*DIM, bk + l*DIM, bv + l*DIM,
            qf, kf, kg, vf);
        attn_kernel<<<gA, 128, ATTN_SMEM>>>(qf, kf, kg, vf, yh, yl);
        mma_gemm<512,0><<<gD, 256, GEMM_SMEM>>>(yh, yl, wh+base+OO, wl+base+OO, bo + l*DIM, t, nullptr, nullptr, DIM, DIM);
        ln_kernel<<<TOK, 128>>>(x, t, ln1w + l*DIM, ln1b + l*DIM, x, xh, xl);
        mma_gemm<512,2><<<gF1, 256, GEMM_SMEM>>>(xh, xl, wh+base+O1, wl+base+O1, b1 + l*FF, nullptr, hh, hl, FFP, FF);
        mma_gemm<256,0><<<gD, 256, GEMM_SMEM>>>(hh, hl, wh+base+O2, wl+base+O2, b2 + l*DIM, t, nullptr, nullptr, DIM, DIM);
        float* lnout = (l == NL-1) ? out : x;
        ln_kernel<<<TOK, 128>>>(x, t, ln2w + l*DIM, ln2b + l*DIM, lnout, xh, xl);
    }
}